// round 1
// baseline (speedup 1.0000x reference)
#include <cuda_runtime.h>
#include <math.h>

#define B_    4
#define S_    2048
#define DIM_  1024
#define H_    16
#define HD_   64
#define BSD   (B_ * S_ * DIM_)   // 8,388,608 floats per activation buffer

// Scratch (no cudaMalloc allowed)
__device__ float g_q[BSD];
__device__ float g_k[BSD];
__device__ float g_v[BSD];
__device__ float g_ctx[BSD];

// ---------------------------------------------------------------------------
// SGEMM: C[m][n] = sum_k A[m][k] * W[n][k]   (A: MxK row-major, W: NxK row-major)
// 128x128 block tile, BK=16, 256 threads, 8x8 per-thread tile (split 4+4).
// grid.z selects one of up to 3 (W, C) pairs (fused QKV).
// ---------------------------------------------------------------------------
__global__ __launch_bounds__(256) void sgemm_nt(
    const float* __restrict__ A,
    const float* __restrict__ W0, const float* __restrict__ W1, const float* __restrict__ W2,
    float* __restrict__ C0, float* __restrict__ C1, float* __restrict__ C2,
    int M, int N, int K)
{
    const float* W = W0;
    float* C = C0;
    if (blockIdx.z == 1) { W = W1; C = C1; }
    else if (blockIdx.z == 2) { W = W2; C = C2; }

    __shared__ float As[16][128];   // As[k][m]
    __shared__ float Bs[16][128];   // Bs[k][n]

    const int tid = threadIdx.x;
    const int m0 = blockIdx.y * 128;
    const int n0 = blockIdx.x * 128;

    // Loader mapping: each thread loads 2 float4 per tile for A and for W.
    const int lr = tid >> 2;            // 0..63
    const int lc = (tid & 3) * 4;       // {0,4,8,12}
    const float* Aptr = A + (size_t)(m0 + lr) * K + lc;
    const float* Wptr = W + (size_t)(n0 + lr) * K + lc;

    // Compute mapping: rows {ry..ry+3, 64+ry..64+ry+3}, cols {cx..cx+3, 64+cx..}
    const int ry = (tid >> 4) * 4;      // 0..60
    const int cx = (tid & 15) * 4;      // 0..60

    float acc[8][8];
#pragma unroll
    for (int i = 0; i < 8; i++)
#pragma unroll
        for (int j = 0; j < 8; j++) acc[i][j] = 0.f;

    const int KT = K >> 4;
    float4 a0 = *(const float4*)(Aptr);
    float4 a1 = *(const float4*)(Aptr + (size_t)64 * K);
    float4 b0 = *(const float4*)(Wptr);
    float4 b1 = *(const float4*)(Wptr + (size_t)64 * K);

    for (int kt = 0; kt < KT; kt++) {
        // store current tile (transposed)
        As[lc + 0][lr] = a0.x; As[lc + 1][lr] = a0.y; As[lc + 2][lr] = a0.z; As[lc + 3][lr] = a0.w;
        As[lc + 0][lr + 64] = a1.x; As[lc + 1][lr + 64] = a1.y; As[lc + 2][lr + 64] = a1.z; As[lc + 3][lr + 64] = a1.w;
        Bs[lc + 0][lr] = b0.x; Bs[lc + 1][lr] = b0.y; Bs[lc + 2][lr] = b0.z; Bs[lc + 3][lr] = b0.w;
        Bs[lc + 0][lr + 64] = b1.x; Bs[lc + 1][lr + 64] = b1.y; Bs[lc + 2][lr + 64] = b1.z; Bs[lc + 3][lr + 64] = b1.w;
        __syncthreads();

        if (kt + 1 < KT) {
            const int off = (kt + 1) * 16;
            a0 = *(const float4*)(Aptr + off);
            a1 = *(const float4*)(Aptr + (size_t)64 * K + off);
            b0 = *(const float4*)(Wptr + off);
            b1 = *(const float4*)(Wptr + (size_t)64 * K + off);
        }

#pragma unroll
        for (int kk = 0; kk < 16; kk++) {
            float ar[8], br[8];
            *(float4*)&ar[0] = *(const float4*)&As[kk][ry];
            *(float4*)&ar[4] = *(const float4*)&As[kk][ry + 64];
            *(float4*)&br[0] = *(const float4*)&Bs[kk][cx];
            *(float4*)&br[4] = *(const float4*)&Bs[kk][cx + 64];
#pragma unroll
            for (int i = 0; i < 8; i++)
#pragma unroll
                for (int j = 0; j < 8; j++)
                    acc[i][j] = fmaf(ar[i], br[j], acc[i][j]);
        }
        __syncthreads();
    }

#pragma unroll
    for (int ii = 0; ii < 8; ii++) {
        const int row = m0 + ((ii < 4) ? (ry + ii) : (64 + ry + ii - 4));
        float4 c0 = make_float4(acc[ii][0], acc[ii][1], acc[ii][2], acc[ii][3]);
        float4 c1 = make_float4(acc[ii][4], acc[ii][5], acc[ii][6], acc[ii][7]);
        *(float4*)&C[(size_t)row * N + n0 + cx]      = c0;
        *(float4*)&C[(size_t)row * N + n0 + 64 + cx] = c1;
    }
}

// ---------------------------------------------------------------------------
// RoPE (in-place on q and k). One thread per (b,s,h,i) pair, i in [0,32).
// ---------------------------------------------------------------------------
__global__ __launch_bounds__(256) void rope_kernel(float* __restrict__ q, float* __restrict__ k)
{
    const int idx = blockIdx.x * blockDim.x + threadIdx.x;
    if (idx >= B_ * S_ * H_ * 32) return;
    const int i = idx & 31;
    const int h = (idx >> 5) & (H_ - 1);
    const int s = (idx >> 9) & (S_ - 1);
    const int b = idx >> 20;

    // angle = s * 10000^(-2i/64), computed in fp64 then range-reduced
    const double inv = exp(-((double)(2 * i) / 64.0) * 9.210340371976184); // ln(10000)
    double ang = (double)s * inv;
    const double tp = 6.283185307179586476925287;
    ang -= floor(ang / tp) * tp;
    float c, sn;
    sincosf((float)ang, &sn, &c);

    const size_t off = ((size_t)(b * S_ + s)) * DIM_ + h * HD_ + i;
    float q1 = q[off], q2 = q[off + 32];
    q[off]      = q1 * c - q2 * sn;
    q[off + 32] = q2 * c + q1 * sn;
    float k1 = k[off], k2 = k[off + 32];
    k[off]      = k1 * c - k2 * sn;
    k[off + 32] = k2 * c + k1 * sn;
}

// ---------------------------------------------------------------------------
// Flash attention, fp32, causal. Block: 64 q-rows of one (b,h); 256 threads.
// Thread grid 16x16; each thread owns a 4x4 score tile and 4x4 O tile.
// K stored d-major (Ks[d][c]); P reuses the K buffer (48KB static smem total).
// ---------------------------------------------------------------------------
__global__ __launch_bounds__(256) void flash_attn(
    const float* __restrict__ q, const float* __restrict__ k,
    const float* __restrict__ v, float* __restrict__ o)
{
    const int qt = blockIdx.x;
    const int bh = blockIdx.y;
    const int b = bh >> 4, h = bh & (H_ - 1);
    const size_t base = (size_t)b * S_ * DIM_ + h * HD_;
    const int q0 = qt * 64;

    __shared__ float Qs[HD_][64];   // Qs[d][r]
    __shared__ float KPs[64][64];   // phase 1: Ks[d][c];  phase 2: Ps[r][c]
    __shared__ float Vs[64][HD_];   // Vs[c][d]

    const int tid = threadIdx.x;
    const int ty = tid >> 4;        // 0..15
    const int tx = tid & 15;        // 0..15

    // Load Q tile (transposed store, conflict-free: lanes vary over r)
    for (int i = tid; i < 1024; i += 256) {
        const int r = i & 63, d4 = i >> 6;
        float4 t4 = *(const float4*)(q + base + (size_t)(q0 + r) * DIM_ + d4 * 4);
        Qs[d4 * 4 + 0][r] = t4.x; Qs[d4 * 4 + 1][r] = t4.y;
        Qs[d4 * 4 + 2][r] = t4.z; Qs[d4 * 4 + 3][r] = t4.w;
    }

    float m_i[4], l_i[4], o_acc[4][4];
#pragma unroll
    for (int i = 0; i < 4; i++) {
        m_i[i] = -1e30f; l_i[i] = 0.f;
#pragma unroll
        for (int j = 0; j < 4; j++) o_acc[i][j] = 0.f;
    }

    const int nkt = qt + 1;   // causal: only tiles with k0 <= q0
    for (int kt = 0; kt < nkt; kt++) {
        const int k0 = kt * 64;
        __syncthreads();   // previous PV done (also covers Q store on iter 0)

        // K tile transposed, V tile row-major
        for (int i = tid; i < 1024; i += 256) {
            const int r = i & 63, d4 = i >> 6;
            float4 t4 = *(const float4*)(k + base + (size_t)(k0 + r) * DIM_ + d4 * 4);
            KPs[d4 * 4 + 0][r] = t4.x; KPs[d4 * 4 + 1][r] = t4.y;
            KPs[d4 * 4 + 2][r] = t4.z; KPs[d4 * 4 + 3][r] = t4.w;
        }
        for (int i = tid; i < 1024; i += 256) {
            const int r = i >> 4, d4 = i & 15;
            *(float4*)&Vs[r][d4 * 4] =
                *(const float4*)(v + base + (size_t)(k0 + r) * DIM_ + d4 * 4);
        }
        __syncthreads();

        // S = Q K^T (64x64), 4x4 per thread
        float s_acc[4][4];
#pragma unroll
        for (int i = 0; i < 4; i++)
#pragma unroll
            for (int j = 0; j < 4; j++) s_acc[i][j] = 0.f;

#pragma unroll 16
        for (int d = 0; d < 64; d++) {
            float qr[4], kr[4];
            *(float4*)&qr[0] = *(const float4*)&Qs[d][ty * 4];
            *(float4*)&kr[0] = *(const float4*)&KPs[d][tx * 4];
#pragma unroll
            for (int i = 0; i < 4; i++)
#pragma unroll
                for (int j = 0; j < 4; j++)
                    s_acc[i][j] = fmaf(qr[i], kr[j], s_acc[i][j]);
        }
        __syncthreads();   // all K reads done before P overwrites KPs

        // scale + causal mask + online softmax (per q-row, reduced over tx)
#pragma unroll
        for (int i = 0; i < 4; i++) {
            const int grow = q0 + ty * 4 + i;
            float rowmax = -1e30f;
#pragma unroll
            for (int j = 0; j < 4; j++) {
                const int gcol = k0 + tx * 4 + j;
                float sv = (gcol <= grow) ? s_acc[i][j] * 0.125f : -1e30f;
                s_acc[i][j] = sv;
                rowmax = fmaxf(rowmax, sv);
            }
#pragma unroll
            for (int off = 8; off > 0; off >>= 1)
                rowmax = fmaxf(rowmax, __shfl_xor_sync(0xffffffffu, rowmax, off, 16));

            const float mnew = fmaxf(m_i[i], rowmax);
            const float corr = __expf(m_i[i] - mnew);
            m_i[i] = mnew;

            float rsum = 0.f;
#pragma unroll
            for (int j = 0; j < 4; j++) {
                float p = __expf(s_acc[i][j] - mnew);
                s_acc[i][j] = p;
                rsum += p;
            }
#pragma unroll
            for (int off = 8; off > 0; off >>= 1)
                rsum += __shfl_xor_sync(0xffffffffu, rsum, off, 16);

            l_i[i] = l_i[i] * corr + rsum;
#pragma unroll
            for (int j = 0; j < 4; j++) o_acc[i][j] *= corr;
        }

        // store P (row-major) into the K buffer
#pragma unroll
        for (int i = 0; i < 4; i++)
            *(float4*)&KPs[ty * 4 + i][tx * 4] =
                make_float4(s_acc[i][0], s_acc[i][1], s_acc[i][2], s_acc[i][3]);
        __syncthreads();

        // O += P V  (O cols = head dims owned by tx)
#pragma unroll 16
        for (int c = 0; c < 64; c++) {
            float vr[4];
            *(float4*)&vr[0] = *(const float4*)&Vs[c][tx * 4];
            const float p0 = KPs[ty * 4 + 0][c];
            const float p1 = KPs[ty * 4 + 1][c];
            const float p2 = KPs[ty * 4 + 2][c];
            const float p3 = KPs[ty * 4 + 3][c];
#pragma unroll
            for (int j = 0; j < 4; j++) {
                o_acc[0][j] = fmaf(p0, vr[j], o_acc[0][j]);
                o_acc[1][j] = fmaf(p1, vr[j], o_acc[1][j]);
                o_acc[2][j] = fmaf(p2, vr[j], o_acc[2][j]);
                o_acc[3][j] = fmaf(p3, vr[j], o_acc[3][j]);
            }
        }
    }

    // epilogue: normalize and write
#pragma unroll
    for (int i = 0; i < 4; i++) {
        const float inv = 1.f / l_i[i];
        float4 w = make_float4(o_acc[i][0] * inv, o_acc[i][1] * inv,
                               o_acc[i][2] * inv, o_acc[i][3] * inv);
        *(float4*)&o[base + (size_t)(q0 + ty * 4 + i) * DIM_ + tx * 4] = w;
    }
}

// ---------------------------------------------------------------------------
extern "C" void kernel_launch(void* const* d_in, const int* in_sizes, int n_in,
                              void* d_out, int out_size)
{
    (void)in_sizes; (void)n_in; (void)out_size;
    const float* x  = (const float*)d_in[0];
    const float* Wq = (const float*)d_in[1];
    const float* Wk = (const float*)d_in[2];
    const float* Wv = (const float*)d_in[3];
    const float* Wo = (const float*)d_in[4];
    float* out = (float*)d_out;

    float *q, *k, *v, *ctx;
    cudaGetSymbolAddress((void**)&q,   g_q);
    cudaGetSymbolAddress((void**)&k,   g_k);
    cudaGetSymbolAddress((void**)&v,   g_v);
    cudaGetSymbolAddress((void**)&ctx, g_ctx);

    const int M = B_ * S_;   // 8192
    const int N = DIM_;      // 1024
    const int K = DIM_;      // 1024

    // Q/K/V projections (fused via grid.z)
    {
        dim3 grid(N / 128, M / 128, 3), block(256);
        sgemm_nt<<<grid, block>>>(x, Wq, Wk, Wv, q, k, v, M, N, K);
    }
    // RoPE in-place on q, k
    {
        const int total = B_ * S_ * H_ * 32;
        rope_kernel<<<(total + 255) / 256, 256>>>(q, k);
    }
    // Causal flash attention -> ctx
    {
        dim3 grid(S_ / 64, B_ * H_), block(256);
        flash_attn<<<grid, block>>>(q, k, v, ctx);
    }
    // Output projection
    {
        dim3 grid(N / 128, M / 128, 1), block(256);
        sgemm_nt<<<grid, block>>>(ctx, Wo, Wo, Wo, out, out, out, M, N, K);
    }
}

// round 2
// speedup vs baseline: 1.0003x; 1.0003x over previous
#include <cuda_runtime.h>
#include <math.h>

#define B_    4
#define S_    2048
#define DIM_  1024
#define H_    16
#define HD_   64
#define BSD   (B_ * S_ * DIM_)   // 8,388,608 floats per activation buffer

// Scratch (no cudaMalloc allowed)
__device__ float g_q[BSD];
__device__ float g_k[BSD];
__device__ float g_v[BSD];
__device__ float g_ctx[BSD];

// ---------------------------------------------------------------------------
// SGEMM: C[m][n] = sum_k A[m][k] * W[n][k]   (A: MxK row-major, W: NxK row-major)
// 128x128 block tile, BK=16, 256 threads, 8x8 per-thread tile (split 4+4).
// grid.z selects one of up to 3 (W, C) pairs (fused QKV).
// ---------------------------------------------------------------------------
__global__ __launch_bounds__(256) void sgemm_nt(
    const float* __restrict__ A,
    const float* __restrict__ W0, const float* __restrict__ W1, const float* __restrict__ W2,
    float* __restrict__ C0, float* __restrict__ C1, float* __restrict__ C2,
    int M, int N, int K)
{
    const float* W = W0;
    float* C = C0;
    if (blockIdx.z == 1) { W = W1; C = C1; }
    else if (blockIdx.z == 2) { W = W2; C = C2; }

    __shared__ float As[16][128];   // As[k][m]
    __shared__ float Bs[16][128];   // Bs[k][n]

    const int tid = threadIdx.x;
    const int m0 = blockIdx.y * 128;
    const int n0 = blockIdx.x * 128;

    // Loader mapping: each thread loads 2 float4 per tile for A and for W.
    const int lr = tid >> 2;            // 0..63
    const int lc = (tid & 3) * 4;       // {0,4,8,12}
    const float* Aptr = A + (size_t)(m0 + lr) * K + lc;
    const float* Wptr = W + (size_t)(n0 + lr) * K + lc;

    // Compute mapping: rows {ry..ry+3, 64+ry..64+ry+3}, cols {cx..cx+3, 64+cx..}
    const int ry = (tid >> 4) * 4;      // 0..60
    const int cx = (tid & 15) * 4;      // 0..60

    float acc[8][8];
#pragma unroll
    for (int i = 0; i < 8; i++)
#pragma unroll
        for (int j = 0; j < 8; j++) acc[i][j] = 0.f;

    const int KT = K >> 4;
    float4 a0 = *(const float4*)(Aptr);
    float4 a1 = *(const float4*)(Aptr + (size_t)64 * K);
    float4 b0 = *(const float4*)(Wptr);
    float4 b1 = *(const float4*)(Wptr + (size_t)64 * K);

    for (int kt = 0; kt < KT; kt++) {
        // store current tile (transposed)
        As[lc + 0][lr] = a0.x; As[lc + 1][lr] = a0.y; As[lc + 2][lr] = a0.z; As[lc + 3][lr] = a0.w;
        As[lc + 0][lr + 64] = a1.x; As[lc + 1][lr + 64] = a1.y; As[lc + 2][lr + 64] = a1.z; As[lc + 3][lr + 64] = a1.w;
        Bs[lc + 0][lr] = b0.x; Bs[lc + 1][lr] = b0.y; Bs[lc + 2][lr] = b0.z; Bs[lc + 3][lr] = b0.w;
        Bs[lc + 0][lr + 64] = b1.x; Bs[lc + 1][lr + 64] = b1.y; Bs[lc + 2][lr + 64] = b1.z; Bs[lc + 3][lr + 64] = b1.w;
        __syncthreads();

        if (kt + 1 < KT) {
            const int off = (kt + 1) * 16;
            a0 = *(const float4*)(Aptr + off);
            a1 = *(const float4*)(Aptr + (size_t)64 * K + off);
            b0 = *(const float4*)(Wptr + off);
            b1 = *(const float4*)(Wptr + (size_t)64 * K + off);
        }

#pragma unroll
        for (int kk = 0; kk < 16; kk++) {
            float ar[8], br[8];
            *(float4*)&ar[0] = *(const float4*)&As[kk][ry];
            *(float4*)&ar[4] = *(const float4*)&As[kk][ry + 64];
            *(float4*)&br[0] = *(const float4*)&Bs[kk][cx];
            *(float4*)&br[4] = *(const float4*)&Bs[kk][cx + 64];
#pragma unroll
            for (int i = 0; i < 8; i++)
#pragma unroll
                for (int j = 0; j < 8; j++)
                    acc[i][j] = fmaf(ar[i], br[j], acc[i][j]);
        }
        __syncthreads();
    }

#pragma unroll
    for (int ii = 0; ii < 8; ii++) {
        const int row = m0 + ((ii < 4) ? (ry + ii) : (64 + ry + ii - 4));
        float4 c0 = make_float4(acc[ii][0], acc[ii][1], acc[ii][2], acc[ii][3]);
        float4 c1 = make_float4(acc[ii][4], acc[ii][5], acc[ii][6], acc[ii][7]);
        *(float4*)&C[(size_t)row * N + n0 + cx]      = c0;
        *(float4*)&C[(size_t)row * N + n0 + 64 + cx] = c1;
    }
}

// ---------------------------------------------------------------------------
// RoPE (in-place on q and k). One thread per (b,s,h,i) pair, i in [0,32).
// ---------------------------------------------------------------------------
__global__ __launch_bounds__(256) void rope_kernel(float* __restrict__ q, float* __restrict__ k)
{
    const int idx = blockIdx.x * blockDim.x + threadIdx.x;
    if (idx >= B_ * S_ * H_ * 32) return;
    const int i = idx & 31;
    const int h = (idx >> 5) & (H_ - 1);
    const int s = (idx >> 9) & (S_ - 1);
    const int b = idx >> 20;

    // angle = s * 10000^(-2i/64), computed in fp64 then range-reduced
    const double inv = exp(-((double)(2 * i) / 64.0) * 9.210340371976184); // ln(10000)
    double ang = (double)s * inv;
    const double tp = 6.283185307179586476925287;
    ang -= floor(ang / tp) * tp;
    float c, sn;
    sincosf((float)ang, &sn, &c);

    const size_t off = ((size_t)(b * S_ + s)) * DIM_ + h * HD_ + i;
    float q1 = q[off], q2 = q[off + 32];
    q[off]      = q1 * c - q2 * sn;
    q[off + 32] = q2 * c + q1 * sn;
    float k1 = k[off], k2 = k[off + 32];
    k[off]      = k1 * c - k2 * sn;
    k[off + 32] = k2 * c + k1 * sn;
}

// ---------------------------------------------------------------------------
// Flash attention, fp32, causal. Block: 64 q-rows of one (b,h); 256 threads.
// Thread grid 16x16; each thread owns a 4x4 score tile and 4x4 O tile.
// K stored d-major (Ks[d][c]); P reuses the K buffer (48KB static smem total).
// ---------------------------------------------------------------------------
__global__ __launch_bounds__(256) void flash_attn(
    const float* __restrict__ q, const float* __restrict__ k,
    const float* __restrict__ v, float* __restrict__ o)
{
    const int qt = blockIdx.x;
    const int bh = blockIdx.y;
    const int b = bh >> 4, h = bh & (H_ - 1);
    const size_t base = (size_t)b * S_ * DIM_ + h * HD_;
    const int q0 = qt * 64;

    __shared__ float Qs[HD_][64];   // Qs[d][r]
    __shared__ float KPs[64][64];   // phase 1: Ks[d][c];  phase 2: Ps[r][c]
    __shared__ float Vs[64][HD_];   // Vs[c][d]

    const int tid = threadIdx.x;
    const int ty = tid >> 4;        // 0..15
    const int tx = tid & 15;        // 0..15

    // Load Q tile (transposed store, conflict-free: lanes vary over r)
    for (int i = tid; i < 1024; i += 256) {
        const int r = i & 63, d4 = i >> 6;
        float4 t4 = *(const float4*)(q + base + (size_t)(q0 + r) * DIM_ + d4 * 4);
        Qs[d4 * 4 + 0][r] = t4.x; Qs[d4 * 4 + 1][r] = t4.y;
        Qs[d4 * 4 + 2][r] = t4.z; Qs[d4 * 4 + 3][r] = t4.w;
    }

    float m_i[4], l_i[4], o_acc[4][4];
#pragma unroll
    for (int i = 0; i < 4; i++) {
        m_i[i] = -1e30f; l_i[i] = 0.f;
#pragma unroll
        for (int j = 0; j < 4; j++) o_acc[i][j] = 0.f;
    }

    const int nkt = qt + 1;   // causal: only tiles with k0 <= q0
    for (int kt = 0; kt < nkt; kt++) {
        const int k0 = kt * 64;
        __syncthreads();   // previous PV done (also covers Q store on iter 0)

        // K tile transposed, V tile row-major
        for (int i = tid; i < 1024; i += 256) {
            const int r = i & 63, d4 = i >> 6;
            float4 t4 = *(const float4*)(k + base + (size_t)(k0 + r) * DIM_ + d4 * 4);
            KPs[d4 * 4 + 0][r] = t4.x; KPs[d4 * 4 + 1][r] = t4.y;
            KPs[d4 * 4 + 2][r] = t4.z; KPs[d4 * 4 + 3][r] = t4.w;
        }
        for (int i = tid; i < 1024; i += 256) {
            const int r = i >> 4, d4 = i & 15;
            *(float4*)&Vs[r][d4 * 4] =
                *(const float4*)(v + base + (size_t)(k0 + r) * DIM_ + d4 * 4);
        }
        __syncthreads();

        // S = Q K^T (64x64), 4x4 per thread
        float s_acc[4][4];
#pragma unroll
        for (int i = 0; i < 4; i++)
#pragma unroll
            for (int j = 0; j < 4; j++) s_acc[i][j] = 0.f;

#pragma unroll 16
        for (int d = 0; d < 64; d++) {
            float qr[4], kr[4];
            *(float4*)&qr[0] = *(const float4*)&Qs[d][ty * 4];
            *(float4*)&kr[0] = *(const float4*)&KPs[d][tx * 4];
#pragma unroll
            for (int i = 0; i < 4; i++)
#pragma unroll
                for (int j = 0; j < 4; j++)
                    s_acc[i][j] = fmaf(qr[i], kr[j], s_acc[i][j]);
        }
        __syncthreads();   // all K reads done before P overwrites KPs

        // scale + causal mask + online softmax (per q-row, reduced over tx)
#pragma unroll
        for (int i = 0; i < 4; i++) {
            const int grow = q0 + ty * 4 + i;
            float rowmax = -1e30f;
#pragma unroll
            for (int j = 0; j < 4; j++) {
                const int gcol = k0 + tx * 4 + j;
                float sv = (gcol <= grow) ? s_acc[i][j] * 0.125f : -1e30f;
                s_acc[i][j] = sv;
                rowmax = fmaxf(rowmax, sv);
            }
#pragma unroll
            for (int off = 8; off > 0; off >>= 1)
                rowmax = fmaxf(rowmax, __shfl_xor_sync(0xffffffffu, rowmax, off, 16));

            const float mnew = fmaxf(m_i[i], rowmax);
            const float corr = __expf(m_i[i] - mnew);
            m_i[i] = mnew;

            float rsum = 0.f;
#pragma unroll
            for (int j = 0; j < 4; j++) {
                float p = __expf(s_acc[i][j] - mnew);
                s_acc[i][j] = p;
                rsum += p;
            }
#pragma unroll
            for (int off = 8; off > 0; off >>= 1)
                rsum += __shfl_xor_sync(0xffffffffu, rsum, off, 16);

            l_i[i] = l_i[i] * corr + rsum;
#pragma unroll
            for (int j = 0; j < 4; j++) o_acc[i][j] *= corr;
        }

        // store P (row-major) into the K buffer
#pragma unroll
        for (int i = 0; i < 4; i++)
            *(float4*)&KPs[ty * 4 + i][tx * 4] =
                make_float4(s_acc[i][0], s_acc[i][1], s_acc[i][2], s_acc[i][3]);
        __syncthreads();

        // O += P V  (O cols = head dims owned by tx)
#pragma unroll 16
        for (int c = 0; c < 64; c++) {
            float vr[4];
            *(float4*)&vr[0] = *(const float4*)&Vs[c][tx * 4];
            const float p0 = KPs[ty * 4 + 0][c];
            const float p1 = KPs[ty * 4 + 1][c];
            const float p2 = KPs[ty * 4 + 2][c];
            const float p3 = KPs[ty * 4 + 3][c];
#pragma unroll
            for (int j = 0; j < 4; j++) {
                o_acc[0][j] = fmaf(p0, vr[j], o_acc[0][j]);
                o_acc[1][j] = fmaf(p1, vr[j], o_acc[1][j]);
                o_acc[2][j] = fmaf(p2, vr[j], o_acc[2][j]);
                o_acc[3][j] = fmaf(p3, vr[j], o_acc[3][j]);
            }
        }
    }

    // epilogue: normalize and write
#pragma unroll
    for (int i = 0; i < 4; i++) {
        const float inv = 1.f / l_i[i];
        float4 w = make_float4(o_acc[i][0] * inv, o_acc[i][1] * inv,
                               o_acc[i][2] * inv, o_acc[i][3] * inv);
        *(float4*)&o[base + (size_t)(q0 + ty * 4 + i) * DIM_ + tx * 4] = w;
    }
}

// ---------------------------------------------------------------------------
extern "C" void kernel_launch(void* const* d_in, const int* in_sizes, int n_in,
                              void* d_out, int out_size)
{
    (void)in_sizes; (void)n_in; (void)out_size;
    const float* x  = (const float*)d_in[0];
    const float* Wq = (const float*)d_in[1];
    const float* Wk = (const float*)d_in[2];
    const float* Wv = (const float*)d_in[3];
    const float* Wo = (const float*)d_in[4];
    float* out = (float*)d_out;

    float *q, *k, *v, *ctx;
    cudaGetSymbolAddress((void**)&q,   g_q);
    cudaGetSymbolAddress((void**)&k,   g_k);
    cudaGetSymbolAddress((void**)&v,   g_v);
    cudaGetSymbolAddress((void**)&ctx, g_ctx);

    const int M = B_ * S_;   // 8192
    const int N = DIM_;      // 1024
    const int K = DIM_;      // 1024

    // Q/K/V projections (fused via grid.z)
    {
        dim3 grid(N / 128, M / 128, 3), block(256);
        sgemm_nt<<<grid, block>>>(x, Wq, Wk, Wv, q, k, v, M, N, K);
    }
    // RoPE in-place on q, k
    {
        const int total = B_ * S_ * H_ * 32;
        rope_kernel<<<(total + 255) / 256, 256>>>(q, k);
    }
    // Causal flash attention -> ctx
    {
        dim3 grid(S_ / 64, B_ * H_), block(256);
        flash_attn<<<grid, block>>>(q, k, v, ctx);
    }
    // Output projection
    {
        dim3 grid(N / 128, M / 128, 1), block(256);
        sgemm_nt<<<grid, block>>>(ctx, Wo, Wo, Wo, out, out, out, M, N, K);
    }
}

// round 4
// speedup vs baseline: 1.4302x; 1.4299x over previous
#include <cuda_runtime.h>
#include <cuda_bf16.h>
#include <math.h>
#include <cstdint>

#define B_    4
#define S_    2048
#define DIM_  1024
#define H_    16
#define HD_   64
#define BSD   (B_ * S_ * DIM_)     // 8,388,608
#define MROWS (B_ * S_)            // 8192
#define NK    (DIM_ * DIM_)        // 1,048,576

// ---------------- device scratch (no cudaMalloc allowed) -------------------
__device__ float g_q[BSD];
__device__ float g_k[BSD];
__device__ float g_v[BSD];
__device__ float g_ctx[BSD];
__device__ __nv_bfloat16 g_xhi[BSD], g_xlo[BSD];
__device__ __nv_bfloat16 g_chi[BSD], g_clo[BSD];
__device__ __nv_bfloat16 g_whi[4 * NK], g_wlo[4 * NK];

// ---------------- PTX helpers (sm_80+ only; NO a-suffix features) ----------
__device__ __forceinline__ uint32_t smem_u32(const void* p) {
    uint32_t a;
    asm("{ .reg .u64 t; cvta.to.shared.u64 t, %1; cvt.u32.u64 %0, t; }"
        : "=r"(a) : "l"(p));
    return a;
}

__device__ __forceinline__ void cp16(uint32_t dst, const void* src) {
    asm volatile("cp.async.cg.shared.global [%0], [%1], 16;"
                 :: "r"(dst), "l"(src));
}
#define CP_COMMIT() asm volatile("cp.async.commit_group;" ::: "memory")
#define CP_WAIT(n)  asm volatile("cp.async.wait_group %0;" :: "n"(n) : "memory")

__device__ __forceinline__ void ldsm_x4(uint32_t* r, uint32_t addr) {
    asm volatile("ldmatrix.sync.aligned.m8n8.x4.shared.b16 {%0,%1,%2,%3}, [%4];"
                 : "=r"(r[0]), "=r"(r[1]), "=r"(r[2]), "=r"(r[3]) : "r"(addr));
}

__device__ __forceinline__ void mma16816(float* c, const uint32_t* a, const uint32_t* b) {
    asm volatile(
        "mma.sync.aligned.m16n8k16.row.col.f32.bf16.bf16.f32 "
        "{%0,%1,%2,%3}, {%4,%5,%6,%7}, {%8,%9}, {%0,%1,%2,%3};"
        : "+f"(c[0]), "+f"(c[1]), "+f"(c[2]), "+f"(c[3])
        : "r"(a[0]), "r"(a[1]), "r"(a[2]), "r"(a[3]), "r"(b[0]), "r"(b[1]));
}

// ---------------------------------------------------------------------------
// split fp32 -> (hi, lo) bf16 pair.  lo = bf16(x - float(hi)).
// ---------------------------------------------------------------------------
__global__ __launch_bounds__(256) void split_bf16(
    const float* __restrict__ src,
    __nv_bfloat16* __restrict__ hi, __nv_bfloat16* __restrict__ lo, int n4)
{
    const int i = blockIdx.x * blockDim.x + threadIdx.x;
    if (i >= n4) return;
    float4 v = ((const float4*)src)[i];
    __nv_bfloat16 h0 = __float2bfloat16(v.x);
    __nv_bfloat16 h1 = __float2bfloat16(v.y);
    __nv_bfloat16 h2 = __float2bfloat16(v.z);
    __nv_bfloat16 h3 = __float2bfloat16(v.w);
    __nv_bfloat16 l0 = __float2bfloat16(v.x - __bfloat162float(h0));
    __nv_bfloat16 l1 = __float2bfloat16(v.y - __bfloat162float(h1));
    __nv_bfloat16 l2 = __float2bfloat16(v.z - __bfloat162float(h2));
    __nv_bfloat16 l3 = __float2bfloat16(v.w - __bfloat162float(h3));
    __nv_bfloat162* hp = (__nv_bfloat162*)(hi + i * 4);
    __nv_bfloat162* lp = (__nv_bfloat162*)(lo + i * 4);
    hp[0] = __nv_bfloat162(h0, h1); hp[1] = __nv_bfloat162(h2, h3);
    lp[0] = __nv_bfloat162(l0, l1); lp[1] = __nv_bfloat162(l2, l3);
}

// ---------------------------------------------------------------------------
// mma.sync bf16x3-compensated GEMM:
//   C[m][n] = sum_k A[m][k] * W[n][k]  via  Ahi*Whi + Ahi*Wlo + Alo*Whi
// CTA 128x128, BK=32, 8 warps (2x4), warp tile 64x32, cp.async double buffer.
// SMEM rows padded to 80B -> ldmatrix conflict-free (80*r mod 128 all distinct).
// grid.z selects one of 3 (W, C) pairs (fused QKV).
// ---------------------------------------------------------------------------
#define BK     32
#define NITER  (DIM_ / BK)          // 32
#define ROWB   80                   // 32 bf16 = 64B data + 16B pad
#define TILEB  (128 * ROWB)         // 10240
#define STAGEB (4 * TILEB)          // 40960: Ahi, Alo, Bhi, Blo
#define GSMEM  (2 * STAGEB)         // 81920

__global__ __launch_bounds__(256, 1) void gemm_bf16x3(
    const __nv_bfloat16* __restrict__ Ahi, const __nv_bfloat16* __restrict__ Alo,
    const __nv_bfloat16* __restrict__ Whi, const __nv_bfloat16* __restrict__ Wlo,
    float* __restrict__ C0, float* __restrict__ C1, float* __restrict__ C2)
{
    extern __shared__ char smem[];
    const int tid  = threadIdx.x;
    const int wid  = tid >> 5;
    const int lane = tid & 31;
    const int qq   = lane >> 3;     // 0..3 (ldmatrix quadrant)
    const int rr   = lane & 7;      // 0..7 (ldmatrix row within quadrant)
    const int wm   = wid >> 2;      // 0..1
    const int wn   = wid & 3;       // 0..3
    const int z    = blockIdx.z;

    const __nv_bfloat16* Wh = Whi + (size_t)z * NK;
    const __nv_bfloat16* Wl = Wlo + (size_t)z * NK;
    float* C = (z == 0) ? C0 : (z == 1) ? C1 : C2;

    const int m0 = blockIdx.y * 128;
    const int n0 = blockIdx.x * 128;
    const uint32_t sb = smem_u32(smem);

    // loader mapping: per stage, each thread moves 2 chunks of 16B per tile
    const int lrow0 = tid >> 2;          // rows 0..63
    const int lc    = tid & 3;           // chunk 0..3 (8 bf16 each)

    float acc[4][4][4];
#pragma unroll
    for (int a = 0; a < 4; a++)
#pragma unroll
        for (int b = 0; b < 4; b++)
#pragma unroll
            for (int c = 0; c < 4; c++) acc[a][b][c] = 0.f;

    // ---- stage loader ----
    auto load_stage = [&](int stage, int kc) {
        const uint32_t d0 = sb + stage * STAGEB;
#pragma unroll
        for (int j = 0; j < 2; j++) {
            const int row = lrow0 + j * 64;
            const uint32_t doff = row * ROWB + lc * 16;
            const size_t ga = (size_t)(m0 + row) * DIM_ + kc + lc * 8;
            const size_t gb = (size_t)(n0 + row) * DIM_ + kc + lc * 8;
            cp16(d0 + doff,             Ahi + ga);
            cp16(d0 + TILEB + doff,     Alo + ga);
            cp16(d0 + 2 * TILEB + doff, Wh + gb);
            cp16(d0 + 3 * TILEB + doff, Wl + gb);
        }
        CP_COMMIT();
    };

    load_stage(0, 0);

    for (int it = 0; it < NITER; it++) {
        if (it + 1 < NITER) {
            load_stage((it + 1) & 1, (it + 1) * BK);
            CP_WAIT(1);
        } else {
            CP_WAIT(0);
        }
        __syncthreads();

        const uint32_t base = sb + (it & 1) * STAGEB;

#pragma unroll
        for (int ks = 0; ks < 2; ks++) {
            uint32_t ah[4][4], al[4][4], bh[4][2], bl[4][2];

            // A fragments: rows wm*64 + mt*16 + (qq&1)*8 + rr, chunk 2ks+(qq>>1)
#pragma unroll
            for (int mt = 0; mt < 4; mt++) {
                const int arow = wm * 64 + mt * 16 + (qq & 1) * 8 + rr;
                const uint32_t off = arow * ROWB + (2 * ks + (qq >> 1)) * 16;
                ldsm_x4(ah[mt], base + off);
                ldsm_x4(al[mt], base + TILEB + off);
            }
            // B fragments: rows wn*32 + np*16 + (qq>>1)*8 + rr, chunk 2ks+(qq&1)
#pragma unroll
            for (int np = 0; np < 2; np++) {
                const int brow = wn * 32 + np * 16 + (qq >> 1) * 8 + rr;
                const uint32_t off = brow * ROWB + (2 * ks + (qq & 1)) * 16;
                uint32_t t[4];
                ldsm_x4(t, base + 2 * TILEB + off);
                bh[2 * np][0] = t[0]; bh[2 * np][1] = t[1];
                bh[2 * np + 1][0] = t[2]; bh[2 * np + 1][1] = t[3];
                ldsm_x4(t, base + 3 * TILEB + off);
                bl[2 * np][0] = t[0]; bl[2 * np][1] = t[1];
                bl[2 * np + 1][0] = t[2]; bl[2 * np + 1][1] = t[3];
            }

#pragma unroll
            for (int mt = 0; mt < 4; mt++)
#pragma unroll
                for (int nt = 0; nt < 4; nt++) {
                    mma16816(acc[mt][nt], ah[mt], bh[nt]);
                    mma16816(acc[mt][nt], ah[mt], bl[nt]);
                    mma16816(acc[mt][nt], al[mt], bh[nt]);
                }
        }
        __syncthreads();
    }

    // epilogue: fp32 accumulators -> C
#pragma unroll
    for (int mt = 0; mt < 4; mt++)
#pragma unroll
        for (int nt = 0; nt < 4; nt++) {
            const int row = m0 + wm * 64 + mt * 16 + (lane >> 2);
            const int col = n0 + wn * 32 + nt * 8 + (lane & 3) * 2;
            *(float2*)&C[(size_t)row * DIM_ + col] =
                make_float2(acc[mt][nt][0], acc[mt][nt][1]);
            *(float2*)&C[(size_t)(row + 8) * DIM_ + col] =
                make_float2(acc[mt][nt][2], acc[mt][nt][3]);
        }
}

// ---------------------------------------------------------------------------
// RoPE (in-place on q and k). One thread per (b,s,h,i) pair, i in [0,32).
// ---------------------------------------------------------------------------
__global__ __launch_bounds__(256) void rope_kernel(float* __restrict__ q, float* __restrict__ k)
{
    const int idx = blockIdx.x * blockDim.x + threadIdx.x;
    if (idx >= B_ * S_ * H_ * 32) return;
    const int i = idx & 31;
    const int h = (idx >> 5) & (H_ - 1);
    const int s = (idx >> 9) & (S_ - 1);
    const int b = idx >> 20;

    const double inv = exp(-((double)(2 * i) / 64.0) * 9.210340371976184); // ln(10000)
    double ang = (double)s * inv;
    const double tp = 6.283185307179586476925287;
    ang -= floor(ang / tp) * tp;
    float c, sn;
    sincosf((float)ang, &sn, &c);

    const size_t off = ((size_t)(b * S_ + s)) * DIM_ + h * HD_ + i;
    float q1 = q[off], q2 = q[off + 32];
    q[off]      = q1 * c - q2 * sn;
    q[off + 32] = q2 * c + q1 * sn;
    float k1 = k[off], k2 = k[off + 32];
    k[off]      = k1 * c - k2 * sn;
    k[off + 32] = k2 * c + k1 * sn;
}

// ---------------------------------------------------------------------------
// Flash attention, fp32, causal (mma.sync port next round).
// ---------------------------------------------------------------------------
__global__ __launch_bounds__(256) void flash_attn(
    const float* __restrict__ q, const float* __restrict__ k,
    const float* __restrict__ v, float* __restrict__ o)
{
    const int qt = blockIdx.x;
    const int bh = blockIdx.y;
    const int b = bh >> 4, h = bh & (H_ - 1);
    const size_t base = (size_t)b * S_ * DIM_ + h * HD_;
    const int q0 = qt * 64;

    __shared__ float Qs[HD_][64];
    __shared__ float KPs[64][64];
    __shared__ float Vs[64][HD_];

    const int tid = threadIdx.x;
    const int ty = tid >> 4;
    const int tx = tid & 15;

    for (int i = tid; i < 1024; i += 256) {
        const int r = i & 63, d4 = i >> 6;
        float4 t4 = *(const float4*)(q + base + (size_t)(q0 + r) * DIM_ + d4 * 4);
        Qs[d4 * 4 + 0][r] = t4.x; Qs[d4 * 4 + 1][r] = t4.y;
        Qs[d4 * 4 + 2][r] = t4.z; Qs[d4 * 4 + 3][r] = t4.w;
    }

    float m_i[4], l_i[4], o_acc[4][4];
#pragma unroll
    for (int i = 0; i < 4; i++) {
        m_i[i] = -1e30f; l_i[i] = 0.f;
#pragma unroll
        for (int j = 0; j < 4; j++) o_acc[i][j] = 0.f;
    }

    const int nkt = qt + 1;
    for (int kt = 0; kt < nkt; kt++) {
        const int k0 = kt * 64;
        __syncthreads();

        for (int i = tid; i < 1024; i += 256) {
            const int r = i & 63, d4 = i >> 6;
            float4 t4 = *(const float4*)(k + base + (size_t)(k0 + r) * DIM_ + d4 * 4);
            KPs[d4 * 4 + 0][r] = t4.x; KPs[d4 * 4 + 1][r] = t4.y;
            KPs[d4 * 4 + 2][r] = t4.z; KPs[d4 * 4 + 3][r] = t4.w;
        }
        for (int i = tid; i < 1024; i += 256) {
            const int r = i >> 4, d4 = i & 15;
            *(float4*)&Vs[r][d4 * 4] =
                *(const float4*)(v + base + (size_t)(k0 + r) * DIM_ + d4 * 4);
        }
        __syncthreads();

        float s_acc[4][4];
#pragma unroll
        for (int i = 0; i < 4; i++)
#pragma unroll
            for (int j = 0; j < 4; j++) s_acc[i][j] = 0.f;

#pragma unroll 16
        for (int d = 0; d < 64; d++) {
            float qr[4], kr[4];
            *(float4*)&qr[0] = *(const float4*)&Qs[d][ty * 4];
            *(float4*)&kr[0] = *(const float4*)&KPs[d][tx * 4];
#pragma unroll
            for (int i = 0; i < 4; i++)
#pragma unroll
                for (int j = 0; j < 4; j++)
                    s_acc[i][j] = fmaf(qr[i], kr[j], s_acc[i][j]);
        }
        __syncthreads();

#pragma unroll
        for (int i = 0; i < 4; i++) {
            const int grow = q0 + ty * 4 + i;
            float rowmax = -1e30f;
#pragma unroll
            for (int j = 0; j < 4; j++) {
                const int gcol = k0 + tx * 4 + j;
                float sv = (gcol <= grow) ? s_acc[i][j] * 0.125f : -1e30f;
                s_acc[i][j] = sv;
                rowmax = fmaxf(rowmax, sv);
            }
#pragma unroll
            for (int off = 8; off > 0; off >>= 1)
                rowmax = fmaxf(rowmax, __shfl_xor_sync(0xffffffffu, rowmax, off, 16));

            const float mnew = fmaxf(m_i[i], rowmax);
            const float corr = __expf(m_i[i] - mnew);
            m_i[i] = mnew;

            float rsum = 0.f;
#pragma unroll
            for (int j = 0; j < 4; j++) {
                float p = __expf(s_acc[i][j] - mnew);
                s_acc[i][j] = p;
                rsum += p;
            }
#pragma unroll
            for (int off = 8; off > 0; off >>= 1)
                rsum += __shfl_xor_sync(0xffffffffu, rsum, off, 16);

            l_i[i] = l_i[i] * corr + rsum;
#pragma unroll
            for (int j = 0; j < 4; j++) o_acc[i][j] *= corr;
        }

#pragma unroll
        for (int i = 0; i < 4; i++)
            *(float4*)&KPs[ty * 4 + i][tx * 4] =
                make_float4(s_acc[i][0], s_acc[i][1], s_acc[i][2], s_acc[i][3]);
        __syncthreads();

#pragma unroll 16
        for (int c = 0; c < 64; c++) {
            float vr[4];
            *(float4*)&vr[0] = *(const float4*)&Vs[c][tx * 4];
            const float p0 = KPs[ty * 4 + 0][c];
            const float p1 = KPs[ty * 4 + 1][c];
            const float p2 = KPs[ty * 4 + 2][c];
            const float p3 = KPs[ty * 4 + 3][c];
#pragma unroll
            for (int j = 0; j < 4; j++) {
                o_acc[0][j] = fmaf(p0, vr[j], o_acc[0][j]);
                o_acc[1][j] = fmaf(p1, vr[j], o_acc[1][j]);
                o_acc[2][j] = fmaf(p2, vr[j], o_acc[2][j]);
                o_acc[3][j] = fmaf(p3, vr[j], o_acc[3][j]);
            }
        }
    }

#pragma unroll
    for (int i = 0; i < 4; i++) {
        const float inv = 1.f / l_i[i];
        float4 w = make_float4(o_acc[i][0] * inv, o_acc[i][1] * inv,
                               o_acc[i][2] * inv, o_acc[i][3] * inv);
        *(float4*)&o[base + (size_t)(q0 + ty * 4 + i) * DIM_ + tx * 4] = w;
    }
}

// ---------------------------------------------------------------------------
extern "C" void kernel_launch(void* const* d_in, const int* in_sizes, int n_in,
                              void* d_out, int out_size)
{
    (void)in_sizes; (void)n_in; (void)out_size;
    const float* x  = (const float*)d_in[0];
    const float* Wq = (const float*)d_in[1];
    const float* Wk = (const float*)d_in[2];
    const float* Wv = (const float*)d_in[3];
    const float* Wo = (const float*)d_in[4];
    float* out = (float*)d_out;

    float *q, *k, *v, *ctx;
    __nv_bfloat16 *xhi, *xlo, *chi, *clo, *whi, *wlo;
    cudaGetSymbolAddress((void**)&q,   g_q);
    cudaGetSymbolAddress((void**)&k,   g_k);
    cudaGetSymbolAddress((void**)&v,   g_v);
    cudaGetSymbolAddress((void**)&ctx, g_ctx);
    cudaGetSymbolAddress((void**)&xhi, g_xhi);
    cudaGetSymbolAddress((void**)&xlo, g_xlo);
    cudaGetSymbolAddress((void**)&chi, g_chi);
    cudaGetSymbolAddress((void**)&clo, g_clo);
    cudaGetSymbolAddress((void**)&whi, g_whi);
    cudaGetSymbolAddress((void**)&wlo, g_wlo);

    cudaFuncSetAttribute(gemm_bf16x3, cudaFuncAttributeMaxDynamicSharedMemorySize, GSMEM);

    // split inputs to bf16 hi/lo
    {
        const int n4x = BSD / 4, n4w = NK / 4;
        split_bf16<<<(n4x + 255) / 256, 256>>>(x,  xhi, xlo, n4x);
        split_bf16<<<(n4w + 255) / 256, 256>>>(Wq, whi + 0 * (size_t)NK, wlo + 0 * (size_t)NK, n4w);
        split_bf16<<<(n4w + 255) / 256, 256>>>(Wk, whi + 1 * (size_t)NK, wlo + 1 * (size_t)NK, n4w);
        split_bf16<<<(n4w + 255) / 256, 256>>>(Wv, whi + 2 * (size_t)NK, wlo + 2 * (size_t)NK, n4w);
        split_bf16<<<(n4w + 255) / 256, 256>>>(Wo, whi + 3 * (size_t)NK, wlo + 3 * (size_t)NK, n4w);
    }

    // Q/K/V projections on tensor cores (fused via grid.z)
    {
        dim3 grid(DIM_ / 128, MROWS / 128, 3), block(256);
        gemm_bf16x3<<<grid, block, GSMEM>>>(xhi, xlo, whi, wlo, q, k, v);
    }
    // RoPE in-place on q, k
    {
        const int total = B_ * S_ * H_ * 32;
        rope_kernel<<<(total + 255) / 256, 256>>>(q, k);
    }
    // Causal flash attention -> ctx
    {
        dim3 grid(S_ / 64, B_ * H_), block(256);
        flash_attn<<<grid, block>>>(q, k, v, ctx);
    }
    // Output projection on tensor cores
    {
        const int n4c = BSD / 4;
        split_bf16<<<(n4c + 255) / 256, 256>>>(ctx, chi, clo, n4c);
        dim3 grid(DIM_ / 128, MROWS / 128, 1), block(256);
        gemm_bf16x3<<<grid, block, GSMEM>>>(chi, clo, whi + 3 * (size_t)NK, wlo + 3 * (size_t)NK,
                                            out, out, out);
    }
}

// round 5
// speedup vs baseline: 2.7360x; 1.9130x over previous
#include <cuda_runtime.h>
#include <cuda_bf16.h>
#include <math.h>
#include <cstdint>

#define B_    4
#define S_    2048
#define DIM_  1024
#define H_    16
#define HD_   64
#define BSD   (B_ * S_ * DIM_)     // 8,388,608
#define MROWS (B_ * S_)            // 8192
#define NK    (DIM_ * DIM_)        // 1,048,576

// ---------------- device scratch (no cudaMalloc allowed) -------------------
__device__ float g_q[BSD];
__device__ float g_k[BSD];
__device__ float g_v[BSD];
__device__ __nv_bfloat16 g_xhi[BSD], g_xlo[BSD];
__device__ __nv_bfloat16 g_chi[BSD], g_clo[BSD];
__device__ __nv_bfloat16 g_whi[4 * NK], g_wlo[4 * NK];
__device__ __nv_bfloat16 g_qhi[BSD], g_qlo[BSD];
__device__ __nv_bfloat16 g_khi[BSD], g_klo[BSD];
__device__ __nv_bfloat16 g_vThi[BSD], g_vTlo[BSD];   // layout (b,h,d,s)
__device__ float2 g_rtab[S_ * 32];

// ---------------- PTX helpers (sm_80+ only; NO a-suffix features) ----------
__device__ __forceinline__ uint32_t smem_u32(const void* p) {
    uint32_t a;
    asm("{ .reg .u64 t; cvta.to.shared.u64 t, %1; cvt.u32.u64 %0, t; }"
        : "=r"(a) : "l"(p));
    return a;
}
__device__ __forceinline__ void cp16(uint32_t dst, const void* src) {
    asm volatile("cp.async.cg.shared.global [%0], [%1], 16;"
                 :: "r"(dst), "l"(src));
}
#define CP_COMMIT() asm volatile("cp.async.commit_group;" ::: "memory")
#define CP_WAIT(n)  asm volatile("cp.async.wait_group %0;" :: "n"(n) : "memory")

__device__ __forceinline__ void ldsm_x4(uint32_t* r, uint32_t addr) {
    asm volatile("ldmatrix.sync.aligned.m8n8.x4.shared.b16 {%0,%1,%2,%3}, [%4];"
                 : "=r"(r[0]), "=r"(r[1]), "=r"(r[2]), "=r"(r[3]) : "r"(addr));
}
__device__ __forceinline__ void mma16816(float* c, const uint32_t* a, const uint32_t* b) {
    asm volatile(
        "mma.sync.aligned.m16n8k16.row.col.f32.bf16.bf16.f32 "
        "{%0,%1,%2,%3}, {%4,%5,%6,%7}, {%8,%9}, {%0,%1,%2,%3};"
        : "+f"(c[0]), "+f"(c[1]), "+f"(c[2]), "+f"(c[3])
        : "r"(a[0]), "r"(a[1]), "r"(a[2]), "r"(a[3]), "r"(b[0]), "r"(b[1]));
}

__device__ __forceinline__ void pack_hl(uint32_t& ph, uint32_t& pl, float a, float b) {
    __nv_bfloat162 hb = __floats2bfloat162_rn(a, b);
    float2 hf = __bfloat1622float2(hb);
    __nv_bfloat162 lb = __floats2bfloat162_rn(a - hf.x, b - hf.y);
    ph = reinterpret_cast<uint32_t&>(hb);
    pl = reinterpret_cast<uint32_t&>(lb);
}

// ---------------------------------------------------------------------------
// split fp32 -> (hi, lo) bf16 pair.
// ---------------------------------------------------------------------------
__global__ __launch_bounds__(256) void split_bf16(
    const float* __restrict__ src,
    __nv_bfloat16* __restrict__ hi, __nv_bfloat16* __restrict__ lo, int n4)
{
    const int i = blockIdx.x * blockDim.x + threadIdx.x;
    if (i >= n4) return;
    float4 v = ((const float4*)src)[i];
    __nv_bfloat16 h0 = __float2bfloat16(v.x);
    __nv_bfloat16 h1 = __float2bfloat16(v.y);
    __nv_bfloat16 h2 = __float2bfloat16(v.z);
    __nv_bfloat16 h3 = __float2bfloat16(v.w);
    __nv_bfloat16 l0 = __float2bfloat16(v.x - __bfloat162float(h0));
    __nv_bfloat16 l1 = __float2bfloat16(v.y - __bfloat162float(h1));
    __nv_bfloat16 l2 = __float2bfloat16(v.z - __bfloat162float(h2));
    __nv_bfloat16 l3 = __float2bfloat16(v.w - __bfloat162float(h3));
    __nv_bfloat162* hp = (__nv_bfloat162*)(hi + i * 4);
    __nv_bfloat162* lp = (__nv_bfloat162*)(lo + i * 4);
    hp[0] = __nv_bfloat162(h0, h1); hp[1] = __nv_bfloat162(h2, h3);
    lp[0] = __nv_bfloat162(l0, l1); lp[1] = __nv_bfloat162(l2, l3);
}

// ---------------------------------------------------------------------------
// mma.sync bf16x3-compensated GEMM (validated R4). CTA 128x128, BK=32.
// ---------------------------------------------------------------------------
#define BK     32
#define NITER  (DIM_ / BK)
#define ROWB   80
#define TILEB  (128 * ROWB)
#define STAGEB (4 * TILEB)
#define GSMEM  (2 * STAGEB)

__global__ __launch_bounds__(256, 1) void gemm_bf16x3(
    const __nv_bfloat16* __restrict__ Ahi, const __nv_bfloat16* __restrict__ Alo,
    const __nv_bfloat16* __restrict__ Whi, const __nv_bfloat16* __restrict__ Wlo,
    float* __restrict__ C0, float* __restrict__ C1, float* __restrict__ C2)
{
    extern __shared__ char smem[];
    const int tid  = threadIdx.x;
    const int wid  = tid >> 5;
    const int lane = tid & 31;
    const int qq   = lane >> 3;
    const int rr   = lane & 7;
    const int wm   = wid >> 2;
    const int wn   = wid & 3;
    const int z    = blockIdx.z;

    const __nv_bfloat16* Wh = Whi + (size_t)z * NK;
    const __nv_bfloat16* Wl = Wlo + (size_t)z * NK;
    float* C = (z == 0) ? C0 : (z == 1) ? C1 : C2;

    const int m0 = blockIdx.y * 128;
    const int n0 = blockIdx.x * 128;
    const uint32_t sb = smem_u32(smem);

    const int lrow0 = tid >> 2;
    const int lc    = tid & 3;

    float acc[4][4][4];
#pragma unroll
    for (int a = 0; a < 4; a++)
#pragma unroll
        for (int b = 0; b < 4; b++)
#pragma unroll
            for (int c = 0; c < 4; c++) acc[a][b][c] = 0.f;

    auto load_stage = [&](int stage, int kc) {
        const uint32_t d0 = sb + stage * STAGEB;
#pragma unroll
        for (int j = 0; j < 2; j++) {
            const int row = lrow0 + j * 64;
            const uint32_t doff = row * ROWB + lc * 16;
            const size_t ga = (size_t)(m0 + row) * DIM_ + kc + lc * 8;
            const size_t gb = (size_t)(n0 + row) * DIM_ + kc + lc * 8;
            cp16(d0 + doff,             Ahi + ga);
            cp16(d0 + TILEB + doff,     Alo + ga);
            cp16(d0 + 2 * TILEB + doff, Wh + gb);
            cp16(d0 + 3 * TILEB + doff, Wl + gb);
        }
        CP_COMMIT();
    };

    load_stage(0, 0);

    for (int it = 0; it < NITER; it++) {
        if (it + 1 < NITER) {
            load_stage((it + 1) & 1, (it + 1) * BK);
            CP_WAIT(1);
        } else {
            CP_WAIT(0);
        }
        __syncthreads();

        const uint32_t base = sb + (it & 1) * STAGEB;

#pragma unroll
        for (int ks = 0; ks < 2; ks++) {
            uint32_t ah[4][4], al[4][4], bh[4][2], bl[4][2];
#pragma unroll
            for (int mt = 0; mt < 4; mt++) {
                const int arow = wm * 64 + mt * 16 + (qq & 1) * 8 + rr;
                const uint32_t off = arow * ROWB + (2 * ks + (qq >> 1)) * 16;
                ldsm_x4(ah[mt], base + off);
                ldsm_x4(al[mt], base + TILEB + off);
            }
#pragma unroll
            for (int np = 0; np < 2; np++) {
                const int brow = wn * 32 + np * 16 + (qq >> 1) * 8 + rr;
                const uint32_t off = brow * ROWB + (2 * ks + (qq & 1)) * 16;
                uint32_t t[4];
                ldsm_x4(t, base + 2 * TILEB + off);
                bh[2 * np][0] = t[0]; bh[2 * np][1] = t[1];
                bh[2 * np + 1][0] = t[2]; bh[2 * np + 1][1] = t[3];
                ldsm_x4(t, base + 3 * TILEB + off);
                bl[2 * np][0] = t[0]; bl[2 * np][1] = t[1];
                bl[2 * np + 1][0] = t[2]; bl[2 * np + 1][1] = t[3];
            }
#pragma unroll
            for (int mt = 0; mt < 4; mt++)
#pragma unroll
                for (int nt = 0; nt < 4; nt++) {
                    mma16816(acc[mt][nt], ah[mt], bh[nt]);
                    mma16816(acc[mt][nt], ah[mt], bl[nt]);
                    mma16816(acc[mt][nt], al[mt], bh[nt]);
                }
        }
        __syncthreads();
    }

#pragma unroll
    for (int mt = 0; mt < 4; mt++)
#pragma unroll
        for (int nt = 0; nt < 4; nt++) {
            const int row = m0 + wm * 64 + mt * 16 + (lane >> 2);
            const int col = n0 + wn * 32 + nt * 8 + (lane & 3) * 2;
            *(float2*)&C[(size_t)row * DIM_ + col] =
                make_float2(acc[mt][nt][0], acc[mt][nt][1]);
            *(float2*)&C[(size_t)(row + 8) * DIM_ + col] =
                make_float2(acc[mt][nt][2], acc[mt][nt][3]);
        }
}

// ---------------------------------------------------------------------------
// RoPE angle table (fp64 accuracy): tab[s][i] = (cos, sin)
// ---------------------------------------------------------------------------
__global__ void rope_tab(float2* tab)
{
    const int s = blockIdx.x;
    const int i = threadIdx.x;   // 0..31
    const double inv = exp(-((double)(2 * i) / 64.0) * 9.210340371976184);
    double ang = (double)s * inv;
    const double tp = 6.283185307179586476925287;
    ang -= floor(ang / tp) * tp;
    tab[s * 32 + i] = make_float2((float)cos(ang), (float)sin(ang));
}

// ---------------------------------------------------------------------------
// Fused RoPE + bf16 hi/lo split for q (pre-scaled by 0.125) and k.
// One thread per (b,s,h,i2), i2 in [0,16): handles dims {2i2,2i2+1,+32,+33}.
// ---------------------------------------------------------------------------
__global__ __launch_bounds__(256) void rope_split(
    const float* __restrict__ q, const float* __restrict__ k,
    const float2* __restrict__ tab,
    __nv_bfloat16* __restrict__ qhi, __nv_bfloat16* __restrict__ qlo,
    __nv_bfloat16* __restrict__ khi, __nv_bfloat16* __restrict__ klo)
{
    const int idx = blockIdx.x * blockDim.x + threadIdx.x;
    if (idx >= B_ * S_ * H_ * 16) return;
    const int i2 = idx & 15;
    const int h  = (idx >> 4) & 15;
    const int s  = (idx >> 8) & (S_ - 1);
    const int b  = idx >> 19;

    const float2 cs0 = tab[s * 32 + 2 * i2];
    const float2 cs1 = tab[s * 32 + 2 * i2 + 1];

    const size_t off = ((size_t)(b * S_ + s)) * DIM_ + h * HD_ + 2 * i2;

    auto rot_store = [&](const float* src, __nv_bfloat16* dhi, __nv_bfloat16* dlo,
                         float scale) {
        float2 a = *(const float2*)(src + off);
        float2 c = *(const float2*)(src + off + 32);
        float r0  = (a.x * cs0.x - c.x * cs0.y) * scale;
        float r32 = (c.x * cs0.x + a.x * cs0.y) * scale;
        float r1  = (a.y * cs1.x - c.y * cs1.y) * scale;
        float r33 = (c.y * cs1.x + a.y * cs1.y) * scale;
        uint32_t ph, pl;
        pack_hl(ph, pl, r0, r1);
        *(uint32_t*)(dhi + off) = ph;
        *(uint32_t*)(dlo + off) = pl;
        pack_hl(ph, pl, r32, r33);
        *(uint32_t*)(dhi + off + 32) = ph;
        *(uint32_t*)(dlo + off + 32) = pl;
    };
    rot_store(q, qhi, qlo, 0.125f);
    rot_store(k, khi, klo, 1.0f);
}

// ---------------------------------------------------------------------------
// V: fp32 (b,s,h,d) -> bf16 hi/lo transposed (b,h,d,s)
// ---------------------------------------------------------------------------
__global__ __launch_bounds__(256) void vsplit_T(
    const float* __restrict__ v,
    __nv_bfloat16* __restrict__ hiT, __nv_bfloat16* __restrict__ loT)
{
    __shared__ float t[32][65];
    const int s0 = blockIdx.x * 32;
    const int bh = blockIdx.y;
    const int b = bh >> 4, h = bh & 15;
    const float* src = v + (size_t)b * S_ * DIM_ + h * HD_;
    const int tid = threadIdx.x;

    for (int i = tid; i < 2048; i += 256) {
        const int si = i >> 6, d = i & 63;
        t[si][d] = src[(size_t)(s0 + si) * DIM_ + d];
    }
    __syncthreads();
    const size_t obase = ((size_t)bh * 64) * S_ + s0;
    for (int i = tid; i < 2048; i += 256) {
        const int d = i >> 5, si = i & 31;
        const float val = t[si][d];
        const __nv_bfloat16 hb = __float2bfloat16(val);
        hiT[obase + (size_t)d * S_ + si] = hb;
        loT[obase + (size_t)d * S_ + si] = __float2bfloat16(val - __bfloat162float(hb));
    }
}

// ---------------------------------------------------------------------------
// Flash attention on mma.sync bf16x3. CTA: 128 q-rows of one (b,h), 8 warps
// (warp tile 16x64). K-tiles of 64, double-buffered cp.async. Causal.
// Epilogue writes O directly as bf16 hi/lo (feeds output projection).
// ---------------------------------------------------------------------------
#define FROW   144                      // 64 bf16 = 128B + 16B pad
#define QTB    (128 * FROW)             // 18432
#define KTB    (64 * FROW)              // 9216
#define FSTAGE (4 * KTB)                // 36864: khi,klo,vhi,vlo
#define FSMEM  (2 * QTB + 2 * FSTAGE)   // 110592

__global__ __launch_bounds__(256, 2) void flash_mma(
    const __nv_bfloat16* __restrict__ qhi, const __nv_bfloat16* __restrict__ qlo,
    const __nv_bfloat16* __restrict__ khi, const __nv_bfloat16* __restrict__ klo,
    const __nv_bfloat16* __restrict__ vhiT, const __nv_bfloat16* __restrict__ vloT,
    __nv_bfloat16* __restrict__ chi, __nv_bfloat16* __restrict__ clo)
{
    extern __shared__ char smem[];
    const int tid = threadIdx.x, wid = tid >> 5, lane = tid & 31;
    const int qq = lane >> 3, rr = lane & 7;
    const int qt = 15 - blockIdx.x;           // heavy CTAs first
    const int bh = blockIdx.y, b = bh >> 4, h = bh & 15;
    const int q0 = qt * 128;
    const size_t qkbase = (size_t)b * S_ * DIM_ + h * HD_;
    const size_t vbase  = (size_t)bh * 64 * S_;
    const uint32_t sb = smem_u32(smem);
    const uint32_t QHI = 0, QLO = QTB, ST0 = 2 * QTB;

    // prologue: Q tiles (hi+lo)
#pragma unroll
    for (int t = 0; t < 8; t++) {
        const int idx = tid + t * 256;          // 0..2047
        const int op = idx >> 10;               // 0 hi, 1 lo
        const int r = (idx >> 3) & 127, c = idx & 7;
        const __nv_bfloat16* src = (op ? qlo : qhi) + qkbase + (size_t)(q0 + r) * DIM_ + c * 8;
        cp16(sb + (op ? QLO : QHI) + r * FROW + c * 16, src);
    }

    auto load_kv = [&](int kt) {
        const uint32_t d0 = sb + ST0 + (kt & 1) * FSTAGE;
        const int k0 = kt * 64;
#pragma unroll
        for (int t = 0; t < 8; t++) {
            const int idx = tid + t * 256;      // 0..2047
            const int which = idx >> 9;         // 0 khi,1 klo,2 vhi,3 vlo
            const int r = (idx >> 3) & 63, c = idx & 7;
            const uint32_t dst = d0 + which * KTB + r * FROW + c * 16;
            const __nv_bfloat16* src;
            if (which == 0)      src = khi  + qkbase + (size_t)(k0 + r) * DIM_ + c * 8;
            else if (which == 1) src = klo  + qkbase + (size_t)(k0 + r) * DIM_ + c * 8;
            else if (which == 2) src = vhiT + vbase + (size_t)r * S_ + k0 + c * 8;
            else                 src = vloT + vbase + (size_t)r * S_ + k0 + c * 8;
            cp16(dst, src);
        }
    };
    load_kv(0); CP_COMMIT();

    float m[2] = {-1e30f, -1e30f}, l[2] = {0.f, 0.f};
    float oacc[8][4];
#pragma unroll
    for (int nt = 0; nt < 8; nt++)
#pragma unroll
        for (int c = 0; c < 4; c++) oacc[nt][c] = 0.f;

    const int rowlo = q0 + wid * 16 + (lane >> 2);
    const int nkt = 2 * (qt + 1);

    for (int kt = 0; kt < nkt; kt++) {
        if (kt + 1 < nkt) { load_kv(kt + 1); CP_COMMIT(); CP_WAIT(1); }
        else              { CP_WAIT(0); }
        __syncthreads();

        const int k0 = kt * 64;
        const bool active = (k0 <= q0 + wid * 16 + 15);
        if (active) {
            const uint32_t kb = sb + ST0 + (kt & 1) * FSTAGE;

            float sacc[8][4];
#pragma unroll
            for (int nt = 0; nt < 8; nt++)
#pragma unroll
                for (int c = 0; c < 4; c++) sacc[nt][c] = 0.f;

            // ---- S = Q K^T ----
#pragma unroll
            for (int kk = 0; kk < 4; kk++) {
                uint32_t aqh[4], aql[4];
                const uint32_t aoff = (wid * 16 + (qq & 1) * 8 + rr) * FROW
                                    + (2 * kk + (qq >> 1)) * 16;
                ldsm_x4(aqh, sb + QHI + aoff);
                ldsm_x4(aql, sb + QLO + aoff);
#pragma unroll
                for (int np = 0; np < 4; np++) {
                    const uint32_t boff = (np * 16 + (qq >> 1) * 8 + rr) * FROW
                                        + (2 * kk + (qq & 1)) * 16;
                    uint32_t th[4], tl[4];
                    ldsm_x4(th, kb + boff);
                    ldsm_x4(tl, kb + KTB + boff);
                    mma16816(sacc[2 * np],     aqh, &th[0]);
                    mma16816(sacc[2 * np],     aqh, &tl[0]);
                    mma16816(sacc[2 * np],     aql, &th[0]);
                    mma16816(sacc[2 * np + 1], aqh, &th[2]);
                    mma16816(sacc[2 * np + 1], aqh, &tl[2]);
                    mma16816(sacc[2 * np + 1], aql, &th[2]);
                }
            }

            // ---- causal mask (only near-diagonal tiles) ----
            if (k0 + 63 > q0 + wid * 16) {
#pragma unroll
                for (int nt = 0; nt < 8; nt++)
#pragma unroll
                    for (int c = 0; c < 4; c++) {
                        const int gcol = k0 + nt * 8 + (lane & 3) * 2 + (c & 1);
                        const int grow = rowlo + ((c >> 1) << 3);
                        if (gcol > grow) sacc[nt][c] = -1e30f;
                    }
            }

            // ---- online softmax per row-half ----
            float corr[2];
#pragma unroll
            for (int hh = 0; hh < 2; hh++) {
                float rmax = -1e30f;
#pragma unroll
                for (int nt = 0; nt < 8; nt++)
                    rmax = fmaxf(rmax, fmaxf(sacc[nt][2 * hh], sacc[nt][2 * hh + 1]));
                rmax = fmaxf(rmax, __shfl_xor_sync(0xffffffffu, rmax, 1));
                rmax = fmaxf(rmax, __shfl_xor_sync(0xffffffffu, rmax, 2));
                const float mnew = fmaxf(m[hh], rmax);
                corr[hh] = __expf(m[hh] - mnew);
                m[hh] = mnew;
                float rsum = 0.f;
#pragma unroll
                for (int nt = 0; nt < 8; nt++) {
                    float p0 = __expf(sacc[nt][2 * hh]     - mnew);
                    float p1 = __expf(sacc[nt][2 * hh + 1] - mnew);
                    sacc[nt][2 * hh] = p0; sacc[nt][2 * hh + 1] = p1;
                    rsum += p0 + p1;
                }
                rsum += __shfl_xor_sync(0xffffffffu, rsum, 1);
                rsum += __shfl_xor_sync(0xffffffffu, rsum, 2);
                l[hh] = l[hh] * corr[hh] + rsum;
#pragma unroll
                for (int nt = 0; nt < 8; nt++) {
                    oacc[nt][2 * hh]     *= corr[hh];
                    oacc[nt][2 * hh + 1] *= corr[hh];
                }
            }

            // ---- O += P V ----
#pragma unroll
            for (int kk = 0; kk < 4; kk++) {
                uint32_t ph[4], pl[4];
                pack_hl(ph[0], pl[0], sacc[2 * kk][0],     sacc[2 * kk][1]);
                pack_hl(ph[1], pl[1], sacc[2 * kk][2],     sacc[2 * kk][3]);
                pack_hl(ph[2], pl[2], sacc[2 * kk + 1][0], sacc[2 * kk + 1][1]);
                pack_hl(ph[3], pl[3], sacc[2 * kk + 1][2], sacc[2 * kk + 1][3]);
#pragma unroll
                for (int np = 0; np < 4; np++) {
                    const uint32_t boff = (np * 16 + (qq >> 1) * 8 + rr) * FROW
                                        + (2 * kk + (qq & 1)) * 16;
                    uint32_t th[4], tl[4];
                    ldsm_x4(th, kb + 2 * KTB + boff);
                    ldsm_x4(tl, kb + 3 * KTB + boff);
                    mma16816(oacc[2 * np],     ph, &th[0]);
                    mma16816(oacc[2 * np],     ph, &tl[0]);
                    mma16816(oacc[2 * np],     pl, &th[0]);
                    mma16816(oacc[2 * np + 1], ph, &th[2]);
                    mma16816(oacc[2 * np + 1], ph, &tl[2]);
                    mma16816(oacc[2 * np + 1], pl, &th[2]);
                }
            }
        }
        __syncthreads();
    }

    // ---- epilogue: normalize, write bf16 hi/lo directly ----
    const float inv0 = 1.f / l[0], inv1 = 1.f / l[1];
#pragma unroll
    for (int nt = 0; nt < 8; nt++) {
#pragma unroll
        for (int hh = 0; hh < 2; hh++) {
            const float inv = hh ? inv1 : inv0;
            const int row = rowlo + 8 * hh;
            const size_t off = ((size_t)b * S_ + row) * DIM_ + h * HD_
                             + nt * 8 + (lane & 3) * 2;
            uint32_t ph, pl;
            pack_hl(ph, pl, oacc[nt][2 * hh] * inv, oacc[nt][2 * hh + 1] * inv);
            *(uint32_t*)(chi + off) = ph;
            *(uint32_t*)(clo + off) = pl;
        }
    }
}

// ---------------------------------------------------------------------------
extern "C" void kernel_launch(void* const* d_in, const int* in_sizes, int n_in,
                              void* d_out, int out_size)
{
    (void)in_sizes; (void)n_in; (void)out_size;
    const float* x  = (const float*)d_in[0];
    const float* Wq = (const float*)d_in[1];
    const float* Wk = (const float*)d_in[2];
    const float* Wv = (const float*)d_in[3];
    const float* Wo = (const float*)d_in[4];
    float* out = (float*)d_out;

    float *q, *k, *v;
    __nv_bfloat16 *xhi, *xlo, *chi, *clo, *whi, *wlo;
    __nv_bfloat16 *qhi, *qlo, *khi, *klo, *vThi, *vTlo;
    float2* rtab;
    cudaGetSymbolAddress((void**)&q,    g_q);
    cudaGetSymbolAddress((void**)&k,    g_k);
    cudaGetSymbolAddress((void**)&v,    g_v);
    cudaGetSymbolAddress((void**)&xhi,  g_xhi);
    cudaGetSymbolAddress((void**)&xlo,  g_xlo);
    cudaGetSymbolAddress((void**)&chi,  g_chi);
    cudaGetSymbolAddress((void**)&clo,  g_clo);
    cudaGetSymbolAddress((void**)&whi,  g_whi);
    cudaGetSymbolAddress((void**)&wlo,  g_wlo);
    cudaGetSymbolAddress((void**)&qhi,  g_qhi);
    cudaGetSymbolAddress((void**)&qlo,  g_qlo);
    cudaGetSymbolAddress((void**)&khi,  g_khi);
    cudaGetSymbolAddress((void**)&klo,  g_klo);
    cudaGetSymbolAddress((void**)&vThi, g_vThi);
    cudaGetSymbolAddress((void**)&vTlo, g_vTlo);
    cudaGetSymbolAddress((void**)&rtab, g_rtab);

    cudaFuncSetAttribute(gemm_bf16x3, cudaFuncAttributeMaxDynamicSharedMemorySize, GSMEM);
    cudaFuncSetAttribute(flash_mma,  cudaFuncAttributeMaxDynamicSharedMemorySize, FSMEM);

    // split inputs to bf16 hi/lo
    {
        const int n4x = BSD / 4, n4w = NK / 4;
        split_bf16<<<(n4x + 255) / 256, 256>>>(x,  xhi, xlo, n4x);
        split_bf16<<<(n4w + 255) / 256, 256>>>(Wq, whi + 0 * (size_t)NK, wlo + 0 * (size_t)NK, n4w);
        split_bf16<<<(n4w + 255) / 256, 256>>>(Wk, whi + 1 * (size_t)NK, wlo + 1 * (size_t)NK, n4w);
        split_bf16<<<(n4w + 255) / 256, 256>>>(Wv, whi + 2 * (size_t)NK, wlo + 2 * (size_t)NK, n4w);
        split_bf16<<<(n4w + 255) / 256, 256>>>(Wo, whi + 3 * (size_t)NK, wlo + 3 * (size_t)NK, n4w);
    }
    // RoPE angle table
    rope_tab<<<S_, 32>>>(rtab);

    // Q/K/V projections on tensor cores (fused via grid.z)
    {
        dim3 grid(DIM_ / 128, MROWS / 128, 3), block(256);
        gemm_bf16x3<<<grid, block, GSMEM>>>(xhi, xlo, whi, wlo, q, k, v);
    }
    // fused RoPE + split (q scaled by 1/8), and V transpose+split
    {
        const int total = B_ * S_ * H_ * 16;
        rope_split<<<(total + 255) / 256, 256>>>(q, k, rtab, qhi, qlo, khi, klo);
        dim3 gv(S_ / 32, B_ * H_);
        vsplit_T<<<gv, 256>>>(v, vThi, vTlo);
    }
    // flash attention on tensor cores -> chi/clo
    {
        dim3 grid(16, B_ * H_), block(256);
        flash_mma<<<grid, block, FSMEM>>>(qhi, qlo, khi, klo, vThi, vTlo, chi, clo);
    }
    // output projection on tensor cores
    {
        dim3 grid(DIM_ / 128, MROWS / 128, 1), block(256);
        gemm_bf16x3<<<grid, block, GSMEM>>>(chi, clo, whi + 3 * (size_t)NK, wlo + 3 * (size_t)NK,
                                            out, out, out);
    }
}

// round 6
// speedup vs baseline: 3.3169x; 1.2123x over previous
#include <cuda_runtime.h>
#include <cuda_bf16.h>
#include <math.h>
#include <cstdint>

#define B_    4
#define S_    2048
#define DIM_  1024
#define H_    16
#define HD_   64
#define BSD   (B_ * S_ * DIM_)     // 8,388,608
#define MROWS (B_ * S_)            // 8192
#define NK    (DIM_ * DIM_)        // 1,048,576

// ---------------- device scratch (no cudaMalloc allowed) -------------------
__device__ float g_q[BSD];
__device__ float g_k[BSD];
__device__ float g_v[BSD];
__device__ __nv_bfloat16 g_xhi[BSD], g_xlo[BSD];
__device__ __nv_bfloat16 g_chi[BSD], g_clo[BSD];
__device__ __nv_bfloat16 g_whi[4 * NK], g_wlo[4 * NK];
__device__ __nv_bfloat16 g_qhi[BSD], g_qlo[BSD];
__device__ __nv_bfloat16 g_khi[BSD], g_klo[BSD];
__device__ __nv_bfloat16 g_vThi[BSD], g_vTlo[BSD];   // layout (b,h,d,s)
__device__ float2 g_rtab[S_ * 32];

// ---------------- PTX helpers (sm_80+ only; NO a-suffix features) ----------
__device__ __forceinline__ uint32_t smem_u32(const void* p) {
    uint32_t a;
    asm("{ .reg .u64 t; cvta.to.shared.u64 t, %1; cvt.u32.u64 %0, t; }"
        : "=r"(a) : "l"(p));
    return a;
}
__device__ __forceinline__ void cp16(uint32_t dst, const void* src) {
    asm volatile("cp.async.cg.shared.global [%0], [%1], 16;"
                 :: "r"(dst), "l"(src));
}
#define CP_COMMIT() asm volatile("cp.async.commit_group;" ::: "memory")
#define CP_WAIT(n)  asm volatile("cp.async.wait_group %0;" :: "n"(n) : "memory")

__device__ __forceinline__ void ldsm_x4(uint32_t* r, uint32_t addr) {
    asm volatile("ldmatrix.sync.aligned.m8n8.x4.shared.b16 {%0,%1,%2,%3}, [%4];"
                 : "=r"(r[0]), "=r"(r[1]), "=r"(r[2]), "=r"(r[3]) : "r"(addr));
}
__device__ __forceinline__ void mma16816(float* c, const uint32_t* a, const uint32_t* b) {
    asm volatile(
        "mma.sync.aligned.m16n8k16.row.col.f32.bf16.bf16.f32 "
        "{%0,%1,%2,%3}, {%4,%5,%6,%7}, {%8,%9}, {%0,%1,%2,%3};"
        : "+f"(c[0]), "+f"(c[1]), "+f"(c[2]), "+f"(c[3])
        : "r"(a[0]), "r"(a[1]), "r"(a[2]), "r"(a[3]), "r"(b[0]), "r"(b[1]));
}

__device__ __forceinline__ void pack_hl(uint32_t& ph, uint32_t& pl, float a, float b) {
    __nv_bfloat162 hb = __floats2bfloat162_rn(a, b);
    float2 hf = __bfloat1622float2(hb);
    __nv_bfloat162 lb = __floats2bfloat162_rn(a - hf.x, b - hf.y);
    ph = reinterpret_cast<uint32_t&>(hb);
    pl = reinterpret_cast<uint32_t&>(lb);
}

// ---------------------------------------------------------------------------
// split fp32 -> (hi, lo) bf16 pair.
// ---------------------------------------------------------------------------
__global__ __launch_bounds__(256) void split_bf16(
    const float* __restrict__ src,
    __nv_bfloat16* __restrict__ hi, __nv_bfloat16* __restrict__ lo, int n4)
{
    const int i = blockIdx.x * blockDim.x + threadIdx.x;
    if (i >= n4) return;
    float4 v = ((const float4*)src)[i];
    __nv_bfloat16 h0 = __float2bfloat16(v.x);
    __nv_bfloat16 h1 = __float2bfloat16(v.y);
    __nv_bfloat16 h2 = __float2bfloat16(v.z);
    __nv_bfloat16 h3 = __float2bfloat16(v.w);
    __nv_bfloat16 l0 = __float2bfloat16(v.x - __bfloat162float(h0));
    __nv_bfloat16 l1 = __float2bfloat16(v.y - __bfloat162float(h1));
    __nv_bfloat16 l2 = __float2bfloat16(v.z - __bfloat162float(h2));
    __nv_bfloat16 l3 = __float2bfloat16(v.w - __bfloat162float(h3));
    __nv_bfloat162* hp = (__nv_bfloat162*)(hi + i * 4);
    __nv_bfloat162* lp = (__nv_bfloat162*)(lo + i * 4);
    hp[0] = __nv_bfloat162(h0, h1); hp[1] = __nv_bfloat162(h2, h3);
    lp[0] = __nv_bfloat162(l0, l1); lp[1] = __nv_bfloat162(l2, l3);
}

// ---------------------------------------------------------------------------
// mma.sync bf16x3-compensated GEMM. CTA 128x128, BK=32, 8 warps (2x4).
// SMEM: hi|lo interleaved in one 128B row, XOR-swizzled (no padding).
//   phys = row*128 + ((chunk ^ (row&7))*16), chunk 0-3 = hi k-chunks, 4-7 = lo.
// Stage 32KB, double buffer 64KB -> 2 CTAs/SM.
// ---------------------------------------------------------------------------
#define BK     32
#define NITER  (DIM_ / BK)
#define ATILE  16384                // 128 rows * 128B
#define STAGEB (2 * ATILE)          // A + B = 32768
#define GSMEM  (2 * STAGEB)         // 65536

__global__ __launch_bounds__(256, 2) void gemm_bf16x3(
    const __nv_bfloat16* __restrict__ Ahi, const __nv_bfloat16* __restrict__ Alo,
    const __nv_bfloat16* __restrict__ Whi, const __nv_bfloat16* __restrict__ Wlo,
    float* __restrict__ C0, float* __restrict__ C1, float* __restrict__ C2)
{
    extern __shared__ char smem[];
    const int tid  = threadIdx.x;
    const int wid  = tid >> 5;
    const int lane = tid & 31;
    const int qq   = lane >> 3;
    const int rr   = lane & 7;
    const int wm   = wid >> 2;
    const int wn   = wid & 3;
    const int z    = blockIdx.z;

    const __nv_bfloat16* Wh = Whi + (size_t)z * NK;
    const __nv_bfloat16* Wl = Wlo + (size_t)z * NK;
    float* C = (z == 0) ? C0 : (z == 1) ? C1 : C2;

    const int m0 = blockIdx.y * 128;
    const int n0 = blockIdx.x * 128;
    const uint32_t sb = smem_u32(smem);

    float acc[4][4][4];
#pragma unroll
    for (int a = 0; a < 4; a++)
#pragma unroll
        for (int b = 0; b < 4; b++)
#pragma unroll
            for (int c = 0; c < 4; c++) acc[a][b][c] = 0.f;

    // loader: per stage each thread moves 4 A-chunks + 4 B-chunks of 16B
    auto load_stage = [&](int stage, int kc) {
        const uint32_t d0 = sb + stage * STAGEB;
#pragma unroll
        for (int t = 0; t < 4; t++) {
            const int idx = tid + t * 256;          // 0..1023
            const int r = idx >> 3, c = idx & 7;    // c: 0-3 hi, 4-7 lo
            const uint32_t doff = r * 128 + ((c ^ (r & 7)) << 4);
            const size_t goff = (size_t)r * DIM_ + kc + (c & 3) * 8;
            const __nv_bfloat16* srcA = (c < 4 ? Ahi : Alo) + (size_t)m0 * DIM_ + goff;
            const __nv_bfloat16* srcB = (c < 4 ? Wh  : Wl ) + (size_t)n0 * DIM_ + goff;
            cp16(d0 + doff,         srcA);
            cp16(d0 + ATILE + doff, srcB);
        }
        CP_COMMIT();
    };

    load_stage(0, 0);

    for (int it = 0; it < NITER; it++) {
        if (it + 1 < NITER) {
            load_stage((it + 1) & 1, (it + 1) * BK);
            CP_WAIT(1);
        } else {
            CP_WAIT(0);
        }
        __syncthreads();

        const uint32_t abase = sb + (it & 1) * STAGEB;
        const uint32_t bbase = abase + ATILE;

#pragma unroll
        for (int ks = 0; ks < 2; ks++) {
            // B fragments (resident for all mt)
            uint32_t bh[4][2], bl[4][2];
            const int bch = 2 * ks + (qq & 1);
#pragma unroll
            for (int np = 0; np < 2; np++) {
                const int brow = wn * 32 + np * 16 + (qq >> 1) * 8 + rr;
                const uint32_t sw = brow * 128;
                uint32_t t[4];
                ldsm_x4(t, bbase + sw + ((bch ^ (brow & 7)) << 4));
                bh[2 * np][0] = t[0]; bh[2 * np][1] = t[1];
                bh[2 * np + 1][0] = t[2]; bh[2 * np + 1][1] = t[3];
                ldsm_x4(t, bbase + sw + (((bch + 4) ^ (brow & 7)) << 4));
                bl[2 * np][0] = t[0]; bl[2 * np][1] = t[1];
                bl[2 * np + 1][0] = t[2]; bl[2 * np + 1][1] = t[3];
            }
            // A fragments per mt, consumed immediately
            const int ach = 2 * ks + (qq >> 1);
#pragma unroll
            for (int mt = 0; mt < 4; mt++) {
                const int arow = wm * 64 + mt * 16 + (qq & 1) * 8 + rr;
                const uint32_t sw = arow * 128;
                uint32_t ah[4], al[4];
                ldsm_x4(ah, abase + sw + ((ach ^ (arow & 7)) << 4));
                ldsm_x4(al, abase + sw + (((ach + 4) ^ (arow & 7)) << 4));
#pragma unroll
                for (int nt = 0; nt < 4; nt++) {
                    mma16816(acc[mt][nt], ah, bh[nt]);
                    mma16816(acc[mt][nt], ah, bl[nt]);
                    mma16816(acc[mt][nt], al, bh[nt]);
                }
            }
        }
        __syncthreads();
    }

#pragma unroll
    for (int mt = 0; mt < 4; mt++)
#pragma unroll
        for (int nt = 0; nt < 4; nt++) {
            const int row = m0 + wm * 64 + mt * 16 + (lane >> 2);
            const int col = n0 + wn * 32 + nt * 8 + (lane & 3) * 2;
            *(float2*)&C[(size_t)row * DIM_ + col] =
                make_float2(acc[mt][nt][0], acc[mt][nt][1]);
            *(float2*)&C[(size_t)(row + 8) * DIM_ + col] =
                make_float2(acc[mt][nt][2], acc[mt][nt][3]);
        }
}

// ---------------------------------------------------------------------------
// RoPE angle table (fp64 accuracy): tab[s][i] = (cos, sin)
// ---------------------------------------------------------------------------
__global__ void rope_tab(float2* tab)
{
    const int s = blockIdx.x;
    const int i = threadIdx.x;   // 0..31
    const double inv = exp(-((double)(2 * i) / 64.0) * 9.210340371976184);
    double ang = (double)s * inv;
    const double tp = 6.283185307179586476925287;
    ang -= floor(ang / tp) * tp;
    tab[s * 32 + i] = make_float2((float)cos(ang), (float)sin(ang));
}

// ---------------------------------------------------------------------------
// Fused RoPE + bf16 hi/lo split for q (pre-scaled by 0.125) and k.
// ---------------------------------------------------------------------------
__global__ __launch_bounds__(256) void rope_split(
    const float* __restrict__ q, const float* __restrict__ k,
    const float2* __restrict__ tab,
    __nv_bfloat16* __restrict__ qhi, __nv_bfloat16* __restrict__ qlo,
    __nv_bfloat16* __restrict__ khi, __nv_bfloat16* __restrict__ klo)
{
    const int idx = blockIdx.x * blockDim.x + threadIdx.x;
    if (idx >= B_ * S_ * H_ * 16) return;
    const int i2 = idx & 15;
    const int h  = (idx >> 4) & 15;
    const int s  = (idx >> 8) & (S_ - 1);
    const int b  = idx >> 19;

    const float2 cs0 = tab[s * 32 + 2 * i2];
    const float2 cs1 = tab[s * 32 + 2 * i2 + 1];

    const size_t off = ((size_t)(b * S_ + s)) * DIM_ + h * HD_ + 2 * i2;

    auto rot_store = [&](const float* src, __nv_bfloat16* dhi, __nv_bfloat16* dlo,
                         float scale) {
        float2 a = *(const float2*)(src + off);
        float2 c = *(const float2*)(src + off + 32);
        float r0  = (a.x * cs0.x - c.x * cs0.y) * scale;
        float r32 = (c.x * cs0.x + a.x * cs0.y) * scale;
        float r1  = (a.y * cs1.x - c.y * cs1.y) * scale;
        float r33 = (c.y * cs1.x + a.y * cs1.y) * scale;
        uint32_t ph, pl;
        pack_hl(ph, pl, r0, r1);
        *(uint32_t*)(dhi + off) = ph;
        *(uint32_t*)(dlo + off) = pl;
        pack_hl(ph, pl, r32, r33);
        *(uint32_t*)(dhi + off + 32) = ph;
        *(uint32_t*)(dlo + off + 32) = pl;
    };
    rot_store(q, qhi, qlo, 0.125f);
    rot_store(k, khi, klo, 1.0f);
}

// ---------------------------------------------------------------------------
// V: fp32 (b,s,h,d) -> bf16 hi/lo transposed (b,h,d,s)
// ---------------------------------------------------------------------------
__global__ __launch_bounds__(256) void vsplit_T(
    const float* __restrict__ v,
    __nv_bfloat16* __restrict__ hiT, __nv_bfloat16* __restrict__ loT)
{
    __shared__ float t[32][65];
    const int s0 = blockIdx.x * 32;
    const int bh = blockIdx.y;
    const int b = bh >> 4, h = bh & 15;
    const float* src = v + (size_t)b * S_ * DIM_ + h * HD_;
    const int tid = threadIdx.x;

    for (int i = tid; i < 2048; i += 256) {
        const int si = i >> 6, d = i & 63;
        t[si][d] = src[(size_t)(s0 + si) * DIM_ + d];
    }
    __syncthreads();
    const size_t obase = ((size_t)bh * 64) * S_ + s0;
    for (int i = tid; i < 2048; i += 256) {
        const int d = i >> 5, si = i & 31;
        const float val = t[si][d];
        const __nv_bfloat16 hb = __float2bfloat16(val);
        hiT[obase + (size_t)d * S_ + si] = hb;
        loT[obase + (size_t)d * S_ + si] = __float2bfloat16(val - __bfloat162float(hb));
    }
}

// ---------------------------------------------------------------------------
// Flash attention on mma.sync bf16x3 (validated R5, unchanged).
// ---------------------------------------------------------------------------
#define FROW   144                      // 64 bf16 = 128B + 16B pad
#define QTB    (128 * FROW)             // 18432
#define KTB    (64 * FROW)              // 9216
#define FSTAGE (4 * KTB)                // 36864: khi,klo,vhi,vlo
#define FSMEM  (2 * QTB + 2 * FSTAGE)   // 110592

__global__ __launch_bounds__(256, 2) void flash_mma(
    const __nv_bfloat16* __restrict__ qhi, const __nv_bfloat16* __restrict__ qlo,
    const __nv_bfloat16* __restrict__ khi, const __nv_bfloat16* __restrict__ klo,
    const __nv_bfloat16* __restrict__ vhiT, const __nv_bfloat16* __restrict__ vloT,
    __nv_bfloat16* __restrict__ chi, __nv_bfloat16* __restrict__ clo)
{
    extern __shared__ char smem[];
    const int tid = threadIdx.x, wid = tid >> 5, lane = tid & 31;
    const int qq = lane >> 3, rr = lane & 7;
    const int qt = 15 - blockIdx.x;           // heavy CTAs first
    const int bh = blockIdx.y, b = bh >> 4, h = bh & 15;
    const int q0 = qt * 128;
    const size_t qkbase = (size_t)b * S_ * DIM_ + h * HD_;
    const size_t vbase  = (size_t)bh * 64 * S_;
    const uint32_t sb = smem_u32(smem);
    const uint32_t QHI = 0, QLO = QTB, ST0 = 2 * QTB;

#pragma unroll
    for (int t = 0; t < 8; t++) {
        const int idx = tid + t * 256;
        const int op = idx >> 10;
        const int r = (idx >> 3) & 127, c = idx & 7;
        const __nv_bfloat16* src = (op ? qlo : qhi) + qkbase + (size_t)(q0 + r) * DIM_ + c * 8;
        cp16(sb + (op ? QLO : QHI) + r * FROW + c * 16, src);
    }

    auto load_kv = [&](int kt) {
        const uint32_t d0 = sb + ST0 + (kt & 1) * FSTAGE;
        const int k0 = kt * 64;
#pragma unroll
        for (int t = 0; t < 8; t++) {
            const int idx = tid + t * 256;
            const int which = idx >> 9;
            const int r = (idx >> 3) & 63, c = idx & 7;
            const uint32_t dst = d0 + which * KTB + r * FROW + c * 16;
            const __nv_bfloat16* src;
            if (which == 0)      src = khi  + qkbase + (size_t)(k0 + r) * DIM_ + c * 8;
            else if (which == 1) src = klo  + qkbase + (size_t)(k0 + r) * DIM_ + c * 8;
            else if (which == 2) src = vhiT + vbase + (size_t)r * S_ + k0 + c * 8;
            else                 src = vloT + vbase + (size_t)r * S_ + k0 + c * 8;
            cp16(dst, src);
        }
    };
    load_kv(0); CP_COMMIT();

    float m[2] = {-1e30f, -1e30f}, l[2] = {0.f, 0.f};
    float oacc[8][4];
#pragma unroll
    for (int nt = 0; nt < 8; nt++)
#pragma unroll
        for (int c = 0; c < 4; c++) oacc[nt][c] = 0.f;

    const int rowlo = q0 + wid * 16 + (lane >> 2);
    const int nkt = 2 * (qt + 1);

    for (int kt = 0; kt < nkt; kt++) {
        if (kt + 1 < nkt) { load_kv(kt + 1); CP_COMMIT(); CP_WAIT(1); }
        else              { CP_WAIT(0); }
        __syncthreads();

        const int k0 = kt * 64;
        const bool active = (k0 <= q0 + wid * 16 + 15);
        if (active) {
            const uint32_t kb = sb + ST0 + (kt & 1) * FSTAGE;

            float sacc[8][4];
#pragma unroll
            for (int nt = 0; nt < 8; nt++)
#pragma unroll
                for (int c = 0; c < 4; c++) sacc[nt][c] = 0.f;

#pragma unroll
            for (int kk = 0; kk < 4; kk++) {
                uint32_t aqh[4], aql[4];
                const uint32_t aoff = (wid * 16 + (qq & 1) * 8 + rr) * FROW
                                    + (2 * kk + (qq >> 1)) * 16;
                ldsm_x4(aqh, sb + QHI + aoff);
                ldsm_x4(aql, sb + QLO + aoff);
#pragma unroll
                for (int np = 0; np < 4; np++) {
                    const uint32_t boff = (np * 16 + (qq >> 1) * 8 + rr) * FROW
                                        + (2 * kk + (qq & 1)) * 16;
                    uint32_t th[4], tl[4];
                    ldsm_x4(th, kb + boff);
                    ldsm_x4(tl, kb + KTB + boff);
                    mma16816(sacc[2 * np],     aqh, &th[0]);
                    mma16816(sacc[2 * np],     aqh, &tl[0]);
                    mma16816(sacc[2 * np],     aql, &th[0]);
                    mma16816(sacc[2 * np + 1], aqh, &th[2]);
                    mma16816(sacc[2 * np + 1], aqh, &tl[2]);
                    mma16816(sacc[2 * np + 1], aql, &th[2]);
                }
            }

            if (k0 + 63 > q0 + wid * 16) {
#pragma unroll
                for (int nt = 0; nt < 8; nt++)
#pragma unroll
                    for (int c = 0; c < 4; c++) {
                        const int gcol = k0 + nt * 8 + (lane & 3) * 2 + (c & 1);
                        const int grow = rowlo + ((c >> 1) << 3);
                        if (gcol > grow) sacc[nt][c] = -1e30f;
                    }
            }

            float corr[2];
#pragma unroll
            for (int hh = 0; hh < 2; hh++) {
                float rmax = -1e30f;
#pragma unroll
                for (int nt = 0; nt < 8; nt++)
                    rmax = fmaxf(rmax, fmaxf(sacc[nt][2 * hh], sacc[nt][2 * hh + 1]));
                rmax = fmaxf(rmax, __shfl_xor_sync(0xffffffffu, rmax, 1));
                rmax = fmaxf(rmax, __shfl_xor_sync(0xffffffffu, rmax, 2));
                const float mnew = fmaxf(m[hh], rmax);
                corr[hh] = __expf(m[hh] - mnew);
                m[hh] = mnew;
                float rsum = 0.f;
#pragma unroll
                for (int nt = 0; nt < 8; nt++) {
                    float p0 = __expf(sacc[nt][2 * hh]     - mnew);
                    float p1 = __expf(sacc[nt][2 * hh + 1] - mnew);
                    sacc[nt][2 * hh] = p0; sacc[nt][2 * hh + 1] = p1;
                    rsum += p0 + p1;
                }
                rsum += __shfl_xor_sync(0xffffffffu, rsum, 1);
                rsum += __shfl_xor_sync(0xffffffffu, rsum, 2);
                l[hh] = l[hh] * corr[hh] + rsum;
#pragma unroll
                for (int nt = 0; nt < 8; nt++) {
                    oacc[nt][2 * hh]     *= corr[hh];
                    oacc[nt][2 * hh + 1] *= corr[hh];
                }
            }

#pragma unroll
            for (int kk = 0; kk < 4; kk++) {
                uint32_t ph[4], pl[4];
                pack_hl(ph[0], pl[0], sacc[2 * kk][0],     sacc[2 * kk][1]);
                pack_hl(ph[1], pl[1], sacc[2 * kk][2],     sacc[2 * kk][3]);
                pack_hl(ph[2], pl[2], sacc[2 * kk + 1][0], sacc[2 * kk + 1][1]);
                pack_hl(ph[3], pl[3], sacc[2 * kk + 1][2], sacc[2 * kk + 1][3]);
#pragma unroll
                for (int np = 0; np < 4; np++) {
                    const uint32_t boff = (np * 16 + (qq >> 1) * 8 + rr) * FROW
                                        + (2 * kk + (qq & 1)) * 16;
                    uint32_t th[4], tl[4];
                    ldsm_x4(th, kb + 2 * KTB + boff);
                    ldsm_x4(tl, kb + 3 * KTB + boff);
                    mma16816(oacc[2 * np],     ph, &th[0]);
                    mma16816(oacc[2 * np],     ph, &tl[0]);
                    mma16816(oacc[2 * np],     pl, &th[0]);
                    mma16816(oacc[2 * np + 1], ph, &th[2]);
                    mma16816(oacc[2 * np + 1], ph, &tl[2]);
                    mma16816(oacc[2 * np + 1], pl, &th[2]);
                }
            }
        }
        __syncthreads();
    }

    const float inv0 = 1.f / l[0], inv1 = 1.f / l[1];
#pragma unroll
    for (int nt = 0; nt < 8; nt++) {
#pragma unroll
        for (int hh = 0; hh < 2; hh++) {
            const float inv = hh ? inv1 : inv0;
            const int row = rowlo + 8 * hh;
            const size_t off = ((size_t)b * S_ + row) * DIM_ + h * HD_
                             + nt * 8 + (lane & 3) * 2;
            uint32_t ph, pl;
            pack_hl(ph, pl, oacc[nt][2 * hh] * inv, oacc[nt][2 * hh + 1] * inv);
            *(uint32_t*)(chi + off) = ph;
            *(uint32_t*)(clo + off) = pl;
        }
    }
}

// ---------------------------------------------------------------------------
extern "C" void kernel_launch(void* const* d_in, const int* in_sizes, int n_in,
                              void* d_out, int out_size)
{
    (void)in_sizes; (void)n_in; (void)out_size;
    const float* x  = (const float*)d_in[0];
    const float* Wq = (const float*)d_in[1];
    const float* Wk = (const float*)d_in[2];
    const float* Wv = (const float*)d_in[3];
    const float* Wo = (const float*)d_in[4];
    float* out = (float*)d_out;

    float *q, *k, *v;
    __nv_bfloat16 *xhi, *xlo, *chi, *clo, *whi, *wlo;
    __nv_bfloat16 *qhi, *qlo, *khi, *klo, *vThi, *vTlo;
    float2* rtab;
    cudaGetSymbolAddress((void**)&q,    g_q);
    cudaGetSymbolAddress((void**)&k,    g_k);
    cudaGetSymbolAddress((void**)&v,    g_v);
    cudaGetSymbolAddress((void**)&xhi,  g_xhi);
    cudaGetSymbolAddress((void**)&xlo,  g_xlo);
    cudaGetSymbolAddress((void**)&chi,  g_chi);
    cudaGetSymbolAddress((void**)&clo,  g_clo);
    cudaGetSymbolAddress((void**)&whi,  g_whi);
    cudaGetSymbolAddress((void**)&wlo,  g_wlo);
    cudaGetSymbolAddress((void**)&qhi,  g_qhi);
    cudaGetSymbolAddress((void**)&qlo,  g_qlo);
    cudaGetSymbolAddress((void**)&khi,  g_khi);
    cudaGetSymbolAddress((void**)&klo,  g_klo);
    cudaGetSymbolAddress((void**)&vThi, g_vThi);
    cudaGetSymbolAddress((void**)&vTlo, g_vTlo);
    cudaGetSymbolAddress((void**)&rtab, g_rtab);

    cudaFuncSetAttribute(gemm_bf16x3, cudaFuncAttributeMaxDynamicSharedMemorySize, GSMEM);
    cudaFuncSetAttribute(flash_mma,  cudaFuncAttributeMaxDynamicSharedMemorySize, FSMEM);

    // splits (launches 0-4); gemm QKV lands at launch index 5 for ncu -s 5
    {
        const int n4x = BSD / 4, n4w = NK / 4;
        split_bf16<<<(n4x + 255) / 256, 256>>>(x,  xhi, xlo, n4x);
        split_bf16<<<(n4w + 255) / 256, 256>>>(Wq, whi + 0 * (size_t)NK, wlo + 0 * (size_t)NK, n4w);
        split_bf16<<<(n4w + 255) / 256, 256>>>(Wk, whi + 1 * (size_t)NK, wlo + 1 * (size_t)NK, n4w);
        split_bf16<<<(n4w + 255) / 256, 256>>>(Wv, whi + 2 * (size_t)NK, wlo + 2 * (size_t)NK, n4w);
        split_bf16<<<(n4w + 255) / 256, 256>>>(Wo, whi + 3 * (size_t)NK, wlo + 3 * (size_t)NK, n4w);
    }

    // Q/K/V projections on tensor cores (fused via grid.z) — launch #5
    {
        dim3 grid(DIM_ / 128, MROWS / 128, 3), block(256);
        gemm_bf16x3<<<grid, block, GSMEM>>>(xhi, xlo, whi, wlo, q, k, v);
    }
    // RoPE angle table (needed only before rope_split)
    rope_tab<<<S_, 32>>>(rtab);
    // fused RoPE + split (q scaled by 1/8), and V transpose+split
    {
        const int total = B_ * S_ * H_ * 16;
        rope_split<<<(total + 255) / 256, 256>>>(q, k, rtab, qhi, qlo, khi, klo);
        dim3 gv(S_ / 32, B_ * H_);
        vsplit_T<<<gv, 256>>>(v, vThi, vTlo);
    }
    // flash attention on tensor cores -> chi/clo
    {
        dim3 grid(16, B_ * H_), block(256);
        flash_mma<<<grid, block, FSMEM>>>(qhi, qlo, khi, klo, vThi, vTlo, chi, clo);
    }
    // output projection on tensor cores
    {
        dim3 grid(DIM_ / 128, MROWS / 128, 1), block(256);
        gemm_bf16x3<<<grid, block, GSMEM>>>(chi, clo, whi + 3 * (size_t)NK, wlo + 3 * (size_t)NK,
                                            out, out, out);
    }
}